// round 1
// baseline (speedup 1.0000x reference)
#include <cuda_runtime.h>
#include <math.h>

typedef unsigned long long u64;
typedef unsigned int u32;

#define NB 4096
#define NT 64
#define ND 256
#define BT (NB * NT)          // 262144 rows

// ---------------- scratch (static device globals; no allocations) ----------
__device__ float g_tmp[(size_t)BT * ND];
__device__ float g_q  [(size_t)BT * ND];
__device__ float g_k  [(size_t)BT * ND];
__device__ float g_v  [(size_t)BT * ND];
__device__ float g_cv [(size_t)BT];

// ---------------------------------------------------------------------------
// GEMM: C = relu(A[M,256] @ W[256,256] + bias), M = 262144.
// 128x128 block tile, BK=8, 256 threads, 8x8 microtile computed as
// 8 x (4 packed f32x2) accumulators via fma.rn.f32x2 (2x fma-pipe throughput).
// ---------------------------------------------------------------------------
__global__ __launch_bounds__(256, 2)
void gemm_relu_k(const float* __restrict__ A, const float* __restrict__ W,
                 const float* __restrict__ bias, float* __restrict__ C)
{
    __shared__ float As[8][128];
    __shared__ float Bs[8][128];

    const int tid  = threadIdx.x;
    const int tr   = tid >> 4;          // 0..15  -> row group (8 rows)
    const int tc   = tid & 15;          // 0..15  -> col group (8 cols)
    const int m0   = blockIdx.y * 128;
    const int n0   = blockIdx.x * 128;

    const int arow  = tid >> 1;         // 0..127
    const int acolk = (tid & 1) * 4;    // 0 or 4 (k offset)
    const int brow  = tid >> 5;         // 0..7
    const int bcol  = (tid & 31) * 4;   // 0..124

    u64 acc[8][4];
    #pragma unroll
    for (int i = 0; i < 8; i++)
        #pragma unroll
        for (int j = 0; j < 4; j++) acc[i][j] = 0ull;

    const float* Aptr = A + (size_t)(m0 + arow) * ND + acolk;
    const float* Wptr = W + (size_t)brow * ND + n0 + bcol;

    for (int k0 = 0; k0 < ND; k0 += 8) {
        float4 av = *(const float4*)(Aptr + k0);
        float4 bv = *(const float4*)(Wptr + (size_t)k0 * ND);
        As[acolk + 0][arow] = av.x;
        As[acolk + 1][arow] = av.y;
        As[acolk + 2][arow] = av.z;
        As[acolk + 3][arow] = av.w;
        *(float4*)&Bs[brow][bcol] = bv;
        __syncthreads();

        #pragma unroll
        for (int k = 0; k < 8; k++) {
            float4 a0 = *(const float4*)&As[k][tr * 8];
            float4 a1 = *(const float4*)&As[k][tr * 8 + 4];
            const u64* bp = (const u64*)&Bs[k][tc * 8];
            u64 b0 = bp[0], b1 = bp[1], b2 = bp[2], b3 = bp[3];
            float ar8[8] = {a0.x, a0.y, a0.z, a0.w, a1.x, a1.y, a1.z, a1.w};
            #pragma unroll
            for (int ii = 0; ii < 8; ii++) {
                u32 au = __float_as_uint(ar8[ii]);
                u64 ad;
                asm("mov.b64 %0,{%1,%2};" : "=l"(ad) : "r"(au), "r"(au));
                asm("fma.rn.f32x2 %0,%1,%2,%3;" : "=l"(acc[ii][0]) : "l"(ad), "l"(b0), "l"(acc[ii][0]));
                asm("fma.rn.f32x2 %0,%1,%2,%3;" : "=l"(acc[ii][1]) : "l"(ad), "l"(b1), "l"(acc[ii][1]));
                asm("fma.rn.f32x2 %0,%1,%2,%3;" : "=l"(acc[ii][2]) : "l"(ad), "l"(b2), "l"(acc[ii][2]));
                asm("fma.rn.f32x2 %0,%1,%2,%3;" : "=l"(acc[ii][3]) : "l"(ad), "l"(b3), "l"(acc[ii][3]));
            }
        }
        __syncthreads();
    }

    float bmine[8];
    #pragma unroll
    for (int jj = 0; jj < 8; jj++) bmine[jj] = bias[n0 + tc * 8 + jj];

    #pragma unroll
    for (int ii = 0; ii < 8; ii++) {
        float outv[8];
        #pragma unroll
        for (int jp = 0; jp < 4; jp++) {
            u32 lo, hi;
            asm("mov.b64 {%0,%1},%2;" : "=r"(lo), "=r"(hi) : "l"(acc[ii][jp]));
            outv[jp * 2]     = __uint_as_float(lo);
            outv[jp * 2 + 1] = __uint_as_float(hi);
        }
        #pragma unroll
        for (int jj = 0; jj < 8; jj++) {
            float t = outv[jj] + bmine[jj];
            outv[jj] = t > 0.f ? t : 0.f;
        }
        float* cp = C + (size_t)(m0 + tr * 8 + ii) * ND + n0 + tc * 8;
        *(float4*)cp       = make_float4(outv[0], outv[1], outv[2], outv[3]);
        *(float4*)(cp + 4) = make_float4(outv[4], outv[5], outv[6], outv[7]);
    }
}

// ---------------------------------------------------------------------------
// cv = (relu_c @ wc2)  — one warp per row, shuffle reduce.
// ---------------------------------------------------------------------------
__global__ __launch_bounds__(256)
void colvec_k(const float* __restrict__ A, const float* __restrict__ w,
              float* __restrict__ cv)
{
    const int row  = blockIdx.x * 8 + (threadIdx.x >> 5);
    const int lane = threadIdx.x & 31;
    const float* ar = A + (size_t)row * ND;
    float s = 0.f;
    #pragma unroll
    for (int c = lane; c < ND; c += 32) s += ar[c] * w[c];
    #pragma unroll
    for (int o = 16; o; o >>= 1) s += __shfl_xor_sync(0xffffffffu, s, o);
    if (lane == 0) cv[row] = s;
}

// ---------------------------------------------------------------------------
// Fused attention per batch: scores -> softmax -> h_agg, plus coord update.
// One CTA of 256 threads per batch b (4096 CTAs). q/k padded stride 257 to
// avoid 32-way bank conflicts on the D=256 row stride.
// ---------------------------------------------------------------------------
#define QS 257
#define SMF (2 * NT * QS + NT * ND + NT * 65 + NT + NT * 3)
#define ATTN_SMEM (SMF * 4)

__global__ __launch_bounds__(256, 1)
void attn_k(const float* __restrict__ q, const float* __restrict__ k,
            const float* __restrict__ v, const float* __restrict__ cv,
            const float* __restrict__ h, const float* __restrict__ coord,
            float* __restrict__ outh, float* __restrict__ outx)
{
    extern __shared__ float sm[];
    float* sq  = sm;                    // 64 x 257
    float* sk  = sq + NT * QS;          // 64 x 257
    float* sv  = sk + NT * QS;          // 64 x 256
    float* ss  = sv + NT * ND;          // 64 x 65 (scores -> alpha)
    float* scv = ss + NT * 65;          // 64
    float* sco = scv + NT;              // 64 x 3

    const int b = blockIdx.x, tid = threadIdx.x;
    const size_t base = (size_t)b * (NT * ND);

    for (int idx = tid; idx < NT * ND; idx += 256) {
        int r = idx >> 8, c = idx & 255;
        sq[r * QS + c] = q[base + idx];
        sk[r * QS + c] = k[base + idx];
        sv[idx]        = v[base + idx];
    }
    if (tid < NT)      scv[tid] = cv[(size_t)b * NT + tid];
    if (tid < NT * 3)  sco[tid] = coord[(size_t)b * (NT * 3) + tid];
    __syncthreads();

    // ---- scores = q @ k^T (64x64x256), 16x16 threads, 4x4 microtile ----
    {
        const int i0 = (tid >> 4) * 4, j0 = (tid & 15) * 4;
        float acc[4][4] = {};
        for (int d = 0; d < ND; d++) {
            float qa[4], kb[4];
            #pragma unroll
            for (int ii = 0; ii < 4; ii++) qa[ii] = sq[(i0 + ii) * QS + d];
            #pragma unroll
            for (int jj = 0; jj < 4; jj++) kb[jj] = sk[(j0 + jj) * QS + d];
            #pragma unroll
            for (int ii = 0; ii < 4; ii++)
                #pragma unroll
                for (int jj = 0; jj < 4; jj++) acc[ii][jj] += qa[ii] * kb[jj];
        }
        #pragma unroll
        for (int ii = 0; ii < 4; ii++)
            #pragma unroll
            for (int jj = 0; jj < 4; jj++)
                ss[(i0 + ii) * 65 + j0 + jj] = acc[ii][jj];
    }
    __syncthreads();

    // ---- softmax per row + coord aggregation (threads 0..63, one row each) ----
    if (tid < NT) {
        const int i = tid;
        float m = -1e30f;
        for (int j = 0; j < NT; j++) m = fmaxf(m, ss[i * 65 + j]);
        float sum = 0.f;
        for (int j = 0; j < NT; j++) {
            float e = expf(ss[i * 65 + j] - m);
            ss[i * 65 + j] = e;
            sum += e;
        }
        float inv = 1.f / sum;
        float wsum = 0.f, w0 = 0.f, w1 = 0.f, w2 = 0.f;
        for (int j = 0; j < NT; j++) {
            float a = ss[i * 65 + j] * inv;
            ss[i * 65 + j] = a;
            float wv = a * scv[j];
            wsum += wv;
            w0 += wv * sco[j * 3 + 0];
            w1 += wv * sco[j * 3 + 1];
            w2 += wv * sco[j * 3 + 2];
        }
        size_t ob = (size_t)b * (NT * 3) + i * 3;
        outx[ob + 0] = sco[i * 3 + 0] + w0 - sco[i * 3 + 0] * wsum;
        outx[ob + 1] = sco[i * 3 + 1] + w1 - sco[i * 3 + 1] * wsum;
        outx[ob + 2] = sco[i * 3 + 2] + w2 - sco[i * 3 + 2] * wsum;
    }
    __syncthreads();

    // ---- h_agg = alpha @ v (64x64 @ 64x256), 4 rows x 16 cols per thread ----
    {
        const int i0 = (tid >> 4) * 4, d0 = (tid & 15) * 16;
        float hacc[4][16] = {};
        for (int j = 0; j < NT; j++) {
            float a[4];
            #pragma unroll
            for (int ii = 0; ii < 4; ii++) a[ii] = ss[(i0 + ii) * 65 + j];
            const float* vr = &sv[j * ND + d0];
            #pragma unroll
            for (int dq = 0; dq < 4; dq++) {
                float4 vv = *(const float4*)(vr + dq * 4);
                #pragma unroll
                for (int ii = 0; ii < 4; ii++) {
                    hacc[ii][dq * 4 + 0] += a[ii] * vv.x;
                    hacc[ii][dq * 4 + 1] += a[ii] * vv.y;
                    hacc[ii][dq * 4 + 2] += a[ii] * vv.z;
                    hacc[ii][dq * 4 + 3] += a[ii] * vv.w;
                }
            }
        }
        #pragma unroll
        for (int ii = 0; ii < 4; ii++) {
            const size_t o = base + (size_t)(i0 + ii) * ND + d0;
            #pragma unroll
            for (int dq = 0; dq < 4; dq++) {
                float4 hv = *(const float4*)(h + o + dq * 4);
                float4 r  = make_float4(hv.x + hacc[ii][dq * 4 + 0],
                                        hv.y + hacc[ii][dq * 4 + 1],
                                        hv.z + hacc[ii][dq * 4 + 2],
                                        hv.w + hacc[ii][dq * 4 + 3]);
                *(float4*)(outh + o + dq * 4) = r;
            }
        }
    }
}

// ---------------------------------------------------------------------------
extern "C" void kernel_launch(void* const* d_in, const int* in_sizes, int n_in,
                              void* d_out, int out_size)
{
    (void)in_sizes; (void)n_in; (void)out_size;
    const float* h     = (const float*)d_in[0];
    const float* coord = (const float*)d_in[1];
    const float* Wq1 = (const float*)d_in[2];
    const float* bq1 = (const float*)d_in[3];
    const float* Wq2 = (const float*)d_in[4];
    const float* bq2 = (const float*)d_in[5];
    const float* Wk1 = (const float*)d_in[6];
    const float* bk1 = (const float*)d_in[7];
    const float* Wk2 = (const float*)d_in[8];
    const float* bk2 = (const float*)d_in[9];
    const float* Wv1 = (const float*)d_in[10];
    const float* bv1 = (const float*)d_in[11];
    const float* Wv2 = (const float*)d_in[12];
    const float* bv2 = (const float*)d_in[13];
    const float* Wc1 = (const float*)d_in[14];
    const float* bc1 = (const float*)d_in[15];
    const float* wc2 = (const float*)d_in[16];

    float* out_h = (float*)d_out;
    float* out_x = out_h + (size_t)BT * ND;

    float *tmp, *q, *k, *v, *cv;
    cudaGetSymbolAddress((void**)&tmp, g_tmp);
    cudaGetSymbolAddress((void**)&q,   g_q);
    cudaGetSymbolAddress((void**)&k,   g_k);
    cudaGetSymbolAddress((void**)&v,   g_v);
    cudaGetSymbolAddress((void**)&cv,  g_cv);

    dim3 gg(2, BT / 128), gb(256);
    gemm_relu_k<<<gg, gb>>>(h,   Wq1, bq1, tmp);
    gemm_relu_k<<<gg, gb>>>(tmp, Wq2, bq2, q);
    gemm_relu_k<<<gg, gb>>>(h,   Wk1, bk1, tmp);
    gemm_relu_k<<<gg, gb>>>(tmp, Wk2, bk2, k);
    gemm_relu_k<<<gg, gb>>>(h,   Wv1, bv1, tmp);
    gemm_relu_k<<<gg, gb>>>(tmp, Wv2, bv2, v);
    gemm_relu_k<<<gg, gb>>>(v,   Wc1, bc1, tmp);
    colvec_k<<<BT / 8, 256>>>(tmp, wc2, cv);

    cudaFuncSetAttribute(attn_k, cudaFuncAttributeMaxDynamicSharedMemorySize, ATTN_SMEM);
    attn_k<<<NB, 256, ATTN_SMEM>>>(q, k, v, cv, h, coord, out_h, out_x);
}

// round 3
// speedup vs baseline: 1.4669x; 1.4669x over previous
#include <cuda_runtime.h>
#include <math.h>
#include <stdint.h>

typedef unsigned long long u64;
typedef unsigned int u32;

#define NB 4096
#define NT 64
#define ND 256
#define BT (NB * NT)          // 262144 rows

// ---------------- scratch (static device globals; no allocations) ----------
__device__ float g_tmp[(size_t)BT * ND];
__device__ float g_q  [(size_t)BT * ND];
__device__ float g_k  [(size_t)BT * ND];
__device__ float g_v  [(size_t)BT * ND];
__device__ float g_cv [(size_t)BT];
__device__ float g_wt [7][2][ND * ND];   // transposed tf32-split weights [n][k]

// ---------------------------------------------------------------------------
#define SWZ(o) ((o) ^ (((o) >> 3) & 0x70))

__device__ __forceinline__ uint32_t s2u(const void* p) {
    uint32_t a;
    asm("{ .reg .u64 t; cvta.to.shared.u64 t, %1; cvt.u32.u64 %0, t; }" : "=r"(a) : "l"(p));
    return a;
}
__device__ __forceinline__ void cpa16(uint32_t dst, const void* src) {
    asm volatile("cp.async.cg.shared.global [%0], [%1], 16;" :: "r"(dst), "l"(src));
}
__device__ __forceinline__ void splitf(float x, float& hi, float& lo) {
    uint32_t hu;
    asm("cvt.rna.tf32.f32 %0, %1;" : "=r"(hu) : "f"(x));
    hi = __uint_as_float(hu);
    float d = x - hi;
    uint32_t lu;
    asm("cvt.rna.tf32.f32 %0, %1;" : "=r"(lu) : "f"(d));
    lo = __uint_as_float(lu);
}
__device__ __forceinline__ void ldsm4(u32 r[4], uint32_t addr) {
    asm volatile("ldmatrix.sync.aligned.m8n8.x4.shared.b16 {%0,%1,%2,%3}, [%4];"
        : "=r"(r[0]), "=r"(r[1]), "=r"(r[2]), "=r"(r[3]) : "r"(addr));
}
__device__ __forceinline__ void mma8(float c[4], const u32 a[4], u32 b0, u32 b1) {
    asm volatile(
        "mma.sync.aligned.m16n8k8.row.col.f32.tf32.tf32.f32 "
        "{%0,%1,%2,%3}, {%4,%5,%6,%7}, {%8,%9}, {%0,%1,%2,%3};"
        : "+f"(c[0]), "+f"(c[1]), "+f"(c[2]), "+f"(c[3])
        : "r"(a[0]), "r"(a[1]), "r"(a[2]), "r"(a[3]), "r"(b0), "r"(b1));
}

// ---------------------------------------------------------------------------
// prep: Wt_hi[n*256+k], Wt_lo[n*256+k] = tf32 split of W[k*256+n]
// ---------------------------------------------------------------------------
__global__ __launch_bounds__(256)
void prep_w(const float* __restrict__ W, float* __restrict__ Bh, float* __restrict__ Bl)
{
    int idx = blockIdx.x * 256 + threadIdx.x;   // 0..65535
    int k = idx >> 8, n = idx & 255;
    float w = W[idx];
    float hi, lo;
    splitf(w, hi, lo);
    Bh[n * 256 + k] = hi;
    Bl[n * 256 + k] = lo;
}

// ---------------------------------------------------------------------------
// gemm_mma: C = relu(A[262144,256] @ W[256,256] + bias), 3xTF32 mma.sync.
// CTA tile 128x256, 256 threads (8 warps, warp tile 64x64), k-chunk 32,
// 2-stage cp.async pipeline. Stage: A(hi,lo) 32KB + B(hi,lo) 64KB = 96KB.
// ---------------------------------------------------------------------------
#define STG   98304
#define OFF_AL 16384
#define OFF_BH 32768
#define OFF_BL 65536
#define OFF_BIAS (2 * STG)
#define GEMM_SMEM (2 * STG + 1024)

__global__ __launch_bounds__(256, 1)
void gemm_mma(const float* __restrict__ A, const float* __restrict__ Bh,
              const float* __restrict__ Bl, const float* __restrict__ bias,
              float* __restrict__ C)
{
    extern __shared__ char sm[];
    const uint32_t sb = s2u(sm);
    float* sbias = (float*)(sm + OFF_BIAS);
    const int tid = threadIdx.x, wid = tid >> 5, l = tid & 31;
    const int m0 = blockIdx.x * 128;

    const int Wm0 = (wid & 1) * 64;
    const int Wn0 = (wid >> 1) * 64;
    const int am = l & 15, aq = l >> 4;                       // A ldsm lane row/quad
    const int bn = (l & 7) + ((l >> 4) << 3), bq = (l >> 3) & 1; // B ldsm lane row/quad

    sbias[tid] = bias[tid];

    float4 areg[4];

    // ---- helpers as lambdas ----
    auto ldgA = [&](int kc, float4* ar) {
        const int k0 = kc * 32;
        #pragma unroll
        for (int r = 0; r < 4; r++) {
            int f = tid + r * 256;
            int row = f >> 3, kq = f & 7;
            ar[r] = *(const float4*)(A + (size_t)(m0 + row) * 256 + k0 + kq * 4);
        }
    };
    auto cpaB = [&](int kc, uint32_t stage) {
        const int k0 = kc * 32;
        #pragma unroll
        for (int r = 0; r < 8; r++) {
            int f = tid + r * 256;                // 0..2047
            int row = f >> 3, kq = f & 7;
            u32 so = SWZ((u32)(row * 128 + kq * 16));
            cpa16(sb + stage + OFF_BH + so, Bh + (size_t)row * 256 + k0 + kq * 4);
            cpa16(sb + stage + OFF_BL + so, Bl + (size_t)row * 256 + k0 + kq * 4);
        }
        asm volatile("cp.async.commit_group;" ::: "memory");
    };
    auto stsA = [&](const float4* ar, uint32_t stage) {
        #pragma unroll
        for (int r = 0; r < 4; r++) {
            int f = tid + r * 256;
            int row = f >> 3, kq = f & 7;
            float4 h4, l4;
            splitf(ar[r].x, h4.x, l4.x);
            splitf(ar[r].y, h4.y, l4.y);
            splitf(ar[r].z, h4.z, l4.z);
            splitf(ar[r].w, h4.w, l4.w);
            u32 so = SWZ((u32)(row * 128 + kq * 16));
            *(float4*)(sm + stage + so)          = h4;
            *(float4*)(sm + stage + OFF_AL + so) = l4;
        }
    };

    float acc[4][8][4];
    #pragma unroll
    for (int mt = 0; mt < 4; mt++)
        #pragma unroll
        for (int nt = 0; nt < 8; nt++)
            #pragma unroll
            for (int x = 0; x < 4; x++) acc[mt][nt][x] = 0.f;

    // ---- prologue ----
    ldgA(0, areg);
    cpaB(0, 0);
    stsA(areg, 0);
    asm volatile("cp.async.wait_group 0;" ::: "memory");
    __syncthreads();

    // ---- main loop over 8 k-chunks ----
    for (int kc = 0; kc < 8; kc++) {
        const uint32_t cur = (kc & 1) * STG;
        const uint32_t nxt = ((kc + 1) & 1) * STG;
        if (kc < 7) {
            ldgA(kc + 1, areg);
            cpaB(kc + 1, nxt);
        }

        const uint32_t sA = sb + cur;
        const uint32_t sB = sb + cur + OFF_BH;
        #pragma unroll
        for (int ks = 0; ks < 4; ks++) {
            const int cqA = ks * 2 + aq, cqB = ks * 2 + bq;
            u32 Ah[4][4], Al[4][4];
            #pragma unroll
            for (int mt = 0; mt < 4; mt++) {
                u32 off = SWZ((u32)((Wm0 + mt * 16 + am) * 128 + cqA * 16));
                ldsm4(Ah[mt], sA + off);
                ldsm4(Al[mt], sA + OFF_AL + off);
            }
            #pragma unroll
            for (int np = 0; np < 4; np++) {
                u32 offb = SWZ((u32)((Wn0 + np * 16 + bn) * 128 + cqB * 16));
                u32 Bh4[4], Bl4[4];
                ldsm4(Bh4, sB + offb);
                ldsm4(Bl4, sB + 32768 + offb);
                #pragma unroll
                for (int mt = 0; mt < 4; mt++) {
                    mma8(acc[mt][2 * np],     Ah[mt], Bh4[0], Bh4[1]);
                    mma8(acc[mt][2 * np + 1], Ah[mt], Bh4[2], Bh4[3]);
                    mma8(acc[mt][2 * np],     Ah[mt], Bl4[0], Bl4[1]);
                    mma8(acc[mt][2 * np + 1], Ah[mt], Bl4[2], Bl4[3]);
                    mma8(acc[mt][2 * np],     Al[mt], Bh4[0], Bh4[1]);
                    mma8(acc[mt][2 * np + 1], Al[mt], Bh4[2], Bh4[3]);
                }
            }
        }

        if (kc < 7) stsA(areg, nxt);
        asm volatile("cp.async.wait_group 0;" ::: "memory");
        __syncthreads();
    }

    // ---- epilogue: bias + relu, write C ----
    #pragma unroll
    for (int mt = 0; mt < 4; mt++) {
        const int r0 = m0 + Wm0 + mt * 16 + (l >> 2);
        #pragma unroll
        for (int nt = 0; nt < 8; nt++) {
            const int col = Wn0 + nt * 8 + 2 * (l & 3);
            const float b0 = sbias[col], b1 = sbias[col + 1];
            float2 v0, v1;
            v0.x = fmaxf(acc[mt][nt][0] + b0, 0.f);
            v0.y = fmaxf(acc[mt][nt][1] + b1, 0.f);
            v1.x = fmaxf(acc[mt][nt][2] + b0, 0.f);
            v1.y = fmaxf(acc[mt][nt][3] + b1, 0.f);
            *(float2*)(C + (size_t)r0 * 256 + col)       = v0;
            *(float2*)(C + (size_t)(r0 + 8) * 256 + col) = v1;
        }
    }
}

// ---------------------------------------------------------------------------
// cv = (relu_c @ wc2)  — one warp per row, shuffle reduce.
// ---------------------------------------------------------------------------
__global__ __launch_bounds__(256)
void colvec_k(const float* __restrict__ A, const float* __restrict__ w,
              float* __restrict__ cv)
{
    const int row  = blockIdx.x * 8 + (threadIdx.x >> 5);
    const int lane = threadIdx.x & 31;
    const float* ar = A + (size_t)row * ND;
    float s = 0.f;
    #pragma unroll
    for (int c = lane; c < ND; c += 32) s += ar[c] * w[c];
    #pragma unroll
    for (int o = 16; o; o >>= 1) s += __shfl_xor_sync(0xffffffffu, s, o);
    if (lane == 0) cv[row] = s;
}

// ---------------------------------------------------------------------------
// Fused attention per batch (unchanged from round 1 — passing version).
// ---------------------------------------------------------------------------
#define QS 257
#define SMF (2 * NT * QS + NT * ND + NT * 65 + NT + NT * 3)
#define ATTN_SMEM (SMF * 4)

__global__ __launch_bounds__(256, 1)
void attn_k(const float* __restrict__ q, const float* __restrict__ k,
            const float* __restrict__ v, const float* __restrict__ cv,
            const float* __restrict__ h, const float* __restrict__ coord,
            float* __restrict__ outh, float* __restrict__ outx)
{
    extern __shared__ float smf[];
    float* sq  = smf;                   // 64 x 257
    float* sk  = sq + NT * QS;          // 64 x 257
    float* sv  = sk + NT * QS;          // 64 x 256
    float* ss  = sv + NT * ND;          // 64 x 65
    float* scv = ss + NT * 65;          // 64
    float* sco = scv + NT;              // 64 x 3

    const int b = blockIdx.x, tid = threadIdx.x;
    const size_t base = (size_t)b * (NT * ND);

    for (int idx = tid; idx < NT * ND; idx += 256) {
        int r = idx >> 8, c = idx & 255;
        sq[r * QS + c] = q[base + idx];
        sk[r * QS + c] = k[base + idx];
        sv[idx]        = v[base + idx];
    }
    if (tid < NT)      scv[tid] = cv[(size_t)b * NT + tid];
    if (tid < NT * 3)  sco[tid] = coord[(size_t)b * (NT * 3) + tid];
    __syncthreads();

    {
        const int i0 = (tid >> 4) * 4, j0 = (tid & 15) * 4;
        float acc[4][4] = {};
        for (int d = 0; d < ND; d++) {
            float qa[4], kb[4];
            #pragma unroll
            for (int ii = 0; ii < 4; ii++) qa[ii] = sq[(i0 + ii) * QS + d];
            #pragma unroll
            for (int jj = 0; jj < 4; jj++) kb[jj] = sk[(j0 + jj) * QS + d];
            #pragma unroll
            for (int ii = 0; ii < 4; ii++)
                #pragma unroll
                for (int jj = 0; jj < 4; jj++) acc[ii][jj] += qa[ii] * kb[jj];
        }
        #pragma unroll
        for (int ii = 0; ii < 4; ii++)
            #pragma unroll
            for (int jj = 0; jj < 4; jj++)
                ss[(i0 + ii) * 65 + j0 + jj] = acc[ii][jj];
    }
    __syncthreads();

    if (tid < NT) {
        const int i = tid;
        float m = -1e30f;
        for (int j = 0; j < NT; j++) m = fmaxf(m, ss[i * 65 + j]);
        float sum = 0.f;
        for (int j = 0; j < NT; j++) {
            float e = expf(ss[i * 65 + j] - m);
            ss[i * 65 + j] = e;
            sum += e;
        }
        float inv = 1.f / sum;
        float wsum = 0.f, w0 = 0.f, w1 = 0.f, w2 = 0.f;
        for (int j = 0; j < NT; j++) {
            float a = ss[i * 65 + j] * inv;
            ss[i * 65 + j] = a;
            float wv = a * scv[j];
            wsum += wv;
            w0 += wv * sco[j * 3 + 0];
            w1 += wv * sco[j * 3 + 1];
            w2 += wv * sco[j * 3 + 2];
        }
        size_t ob = (size_t)b * (NT * 3) + i * 3;
        outx[ob + 0] = sco[i * 3 + 0] + w0 - sco[i * 3 + 0] * wsum;
        outx[ob + 1] = sco[i * 3 + 1] + w1 - sco[i * 3 + 1] * wsum;
        outx[ob + 2] = sco[i * 3 + 2] + w2 - sco[i * 3 + 2] * wsum;
    }
    __syncthreads();

    {
        const int i0 = (tid >> 4) * 4, d0 = (tid & 15) * 16;
        float hacc[4][16] = {};
        for (int j = 0; j < NT; j++) {
            float a[4];
            #pragma unroll
            for (int ii = 0; ii < 4; ii++) a[ii] = ss[(i0 + ii) * 65 + j];
            const float* vr = &sv[j * ND + d0];
            #pragma unroll
            for (int dq = 0; dq < 4; dq++) {
                float4 vv = *(const float4*)(vr + dq * 4);
                #pragma unroll
                for (int ii = 0; ii < 4; ii++) {
                    hacc[ii][dq * 4 + 0] += a[ii] * vv.x;
                    hacc[ii][dq * 4 + 1] += a[ii] * vv.y;
                    hacc[ii][dq * 4 + 2] += a[ii] * vv.z;
                    hacc[ii][dq * 4 + 3] += a[ii] * vv.w;
                }
            }
        }
        #pragma unroll
        for (int ii = 0; ii < 4; ii++) {
            const size_t o = base + (size_t)(i0 + ii) * ND + d0;
            #pragma unroll
            for (int dq = 0; dq < 4; dq++) {
                float4 hv = *(const float4*)(h + o + dq * 4);
                float4 r  = make_float4(hv.x + hacc[ii][dq * 4 + 0],
                                        hv.y + hacc[ii][dq * 4 + 1],
                                        hv.z + hacc[ii][dq * 4 + 2],
                                        hv.w + hacc[ii][dq * 4 + 3]);
                *(float4*)(outh + o + dq * 4) = r;
            }
        }
    }
}

// ---------------------------------------------------------------------------
extern "C" void kernel_launch(void* const* d_in, const int* in_sizes, int n_in,
                              void* d_out, int out_size)
{
    (void)in_sizes; (void)n_in; (void)out_size;
    const float* h     = (const float*)d_in[0];
    const float* coord = (const float*)d_in[1];
    const float* Wq1 = (const float*)d_in[2];
    const float* bq1 = (const float*)d_in[3];
    const float* Wq2 = (const float*)d_in[4];
    const float* bq2 = (const float*)d_in[5];
    const float* Wk1 = (const float*)d_in[6];
    const float* bk1 = (const float*)d_in[7];
    const float* Wk2 = (const float*)d_in[8];
    const float* bk2 = (const float*)d_in[9];
    const float* Wv1 = (const float*)d_in[10];
    const float* bv1 = (const float*)d_in[11];
    const float* Wv2 = (const float*)d_in[12];
    const float* bv2 = (const float*)d_in[13];
    const float* Wc1 = (const float*)d_in[14];
    const float* bc1 = (const float*)d_in[15];
    const float* wc2 = (const float*)d_in[16];

    float* out_h = (float*)d_out;
    float* out_x = out_h + (size_t)BT * ND;

    float *tmp, *q, *k, *v, *cv, *wt;
    cudaGetSymbolAddress((void**)&tmp, g_tmp);
    cudaGetSymbolAddress((void**)&q,   g_q);
    cudaGetSymbolAddress((void**)&k,   g_k);
    cudaGetSymbolAddress((void**)&v,   g_v);
    cudaGetSymbolAddress((void**)&cv,  g_cv);
    cudaGetSymbolAddress((void**)&wt,  g_wt);

    const float* Ws[7] = {Wq1, Wq2, Wk1, Wk2, Wv1, Wv2, Wc1};
    for (int i = 0; i < 7; i++)
        prep_w<<<256, 256>>>(Ws[i], wt + ((size_t)i * 2 + 0) * ND * ND,
                                     wt + ((size_t)i * 2 + 1) * ND * ND);

    cudaFuncSetAttribute(gemm_mma, cudaFuncAttributeMaxDynamicSharedMemorySize, GEMM_SMEM);
    #define WH(i) (wt + ((size_t)(i) * 2 + 0) * ND * ND)
    #define WL(i) (wt + ((size_t)(i) * 2 + 1) * ND * ND)

    gemm_mma<<<2048, 256, GEMM_SMEM>>>(h,   WH(0), WL(0), bq1, tmp);
    gemm_mma<<<2048, 256, GEMM_SMEM>>>(tmp, WH(1), WL(1), bq2, q);
    gemm_mma<<<2048, 256, GEMM_SMEM>>>(h,   WH(2), WL(2), bk1, tmp);
    gemm_mma<<<2048, 256, GEMM_SMEM>>>(tmp, WH(3), WL(3), bk2, k);
    gemm_mma<<<2048, 256, GEMM_SMEM>>>(h,   WH(4), WL(4), bv1, tmp);
    gemm_mma<<<2048, 256, GEMM_SMEM>>>(tmp, WH(5), WL(5), bv2, v);
    gemm_mma<<<2048, 256, GEMM_SMEM>>>(v,   WH(6), WL(6), bc1, tmp);
    colvec_k<<<BT / 8, 256>>>(tmp, wc2, cv);

    cudaFuncSetAttribute(attn_k, cudaFuncAttributeMaxDynamicSharedMemorySize, ATTN_SMEM);
    attn_k<<<NB, 256, ATTN_SMEM>>>(q, k, v, cv, h, coord, out_h, out_x);
}

// round 4
// speedup vs baseline: 1.9547x; 1.3325x over previous
#include <cuda_runtime.h>
#include <cuda_bf16.h>
#include <math.h>
#include <stdint.h>

typedef unsigned long long u64;
typedef unsigned int u32;

#define NB 4096
#define NT 64
#define ND 256
#define BT (NB * NT)          // 262144 rows

// ---------------- scratch (static device globals; no allocations) ----------
__device__ float g_tmp[(size_t)BT * ND];
__device__ float g_q  [(size_t)BT * ND];
__device__ float g_k  [(size_t)BT * ND];
__device__ float g_v  [(size_t)BT * ND];
__device__ float g_cv [(size_t)BT];
__device__ __nv_bfloat16 g_wbh[7][ND * ND];   // transposed bf16-hi weights [n][k]
__device__ __nv_bfloat16 g_wbl[7][ND * ND];   // transposed bf16-lo weights [n][k]

// ---------------------------------------------------------------------------
#define SWZ64(o) ((o) ^ (((o) >> 3) & 0x30))

__device__ __forceinline__ uint32_t s2u(const void* p) {
    uint32_t a;
    asm("{ .reg .u64 t; cvta.to.shared.u64 t, %1; cvt.u32.u64 %0, t; }" : "=r"(a) : "l"(p));
    return a;
}
__device__ __forceinline__ void cpa16(uint32_t dst, const void* src) {
    asm volatile("cp.async.cg.shared.global [%0], [%1], 16;" :: "r"(dst), "l"(src));
}
__device__ __forceinline__ void ldsm4(u32 r[4], uint32_t addr) {
    asm volatile("ldmatrix.sync.aligned.m8n8.x4.shared.b16 {%0,%1,%2,%3}, [%4];"
        : "=r"(r[0]), "=r"(r[1]), "=r"(r[2]), "=r"(r[3]) : "r"(addr));
}
__device__ __forceinline__ void mma16(float c[4], const u32 a[4], u32 b0, u32 b1) {
    asm volatile(
        "mma.sync.aligned.m16n8k16.row.col.f32.bf16.bf16.f32 "
        "{%0,%1,%2,%3}, {%4,%5,%6,%7}, {%8,%9}, {%0,%1,%2,%3};"
        : "+f"(c[0]), "+f"(c[1]), "+f"(c[2]), "+f"(c[3])
        : "r"(a[0]), "r"(a[1]), "r"(a[2]), "r"(a[3]), "r"(b0), "r"(b1));
}
__device__ __forceinline__ u32 pack2(__nv_bfloat16 a, __nv_bfloat16 b) {
    return (u32)__bfloat16_as_ushort(a) | ((u32)__bfloat16_as_ushort(b) << 16);
}
__device__ __forceinline__ void split_bf(float x, __nv_bfloat16& hi, __nv_bfloat16& lo) {
    hi = __float2bfloat16_rn(x);
    lo = __float2bfloat16_rn(x - __bfloat162float(hi));
}

// ---------------------------------------------------------------------------
// prep: bf16 hi/lo split of W, transposed to [n][k]
// ---------------------------------------------------------------------------
__global__ __launch_bounds__(256)
void prep_w(const float* __restrict__ W, __nv_bfloat16* __restrict__ Bh,
            __nv_bfloat16* __restrict__ Bl)
{
    int idx = blockIdx.x * 256 + threadIdx.x;   // 0..65535
    int k = idx >> 8, n = idx & 255;
    float w = W[idx];
    __nv_bfloat16 hi, lo;
    split_bf(w, hi, lo);
    Bh[n * 256 + k] = hi;
    Bl[n * 256 + k] = lo;
}

// ---------------------------------------------------------------------------
// gemm_mma: C = relu(A[262144,256] @ W[256,256] + bias), bf16x3 mma.sync.
// CTA tile 128x128, 8 warps (warp 64x32), k-chunk 32, 3-stage cp.async,
// occ=2 (96KB smem, ~125 regs). Grid (2048, 2).
// Stage layout (32KB): Ahi[0,8K) Alo[8K,16K) Bhi[16K,24K) Blo[24K,32K)
// ---------------------------------------------------------------------------
#define STG   32768u
#define OFF_AL 8192u
#define OFF_BH 16384u
#define OFF_BIAS (3 * 32768)
#define GEMM_SMEM (3 * 32768 + 512)
#define NKC 8

__global__ __launch_bounds__(256, 2)
void gemm_mma(const float* __restrict__ A, const __nv_bfloat16* __restrict__ Bh,
              const __nv_bfloat16* __restrict__ Bl, const float* __restrict__ bias,
              float* __restrict__ C)
{
    extern __shared__ char sm[];
    const uint32_t sb = s2u(sm);
    float* sbias = (float*)(sm + OFF_BIAS);
    const int tid = threadIdx.x, wid = tid >> 5, l = tid & 31;
    const int m0 = blockIdx.x * 128;
    const int n0 = blockIdx.y * 128;

    const int Wm0 = (wid & 1) * 64;
    const int Wn0 = (wid >> 1) * 32;
    const int am = l & 15, aq = l >> 4;                          // A ldsm row/16B-col
    const int bn = (l & 7) + ((l >> 4) << 3), bq = (l >> 3) & 1; // B ldsm row/16B-col

    if (tid < 128) sbias[tid] = bias[n0 + tid];

    // ---- lambdas ----
    float4 areg[4];
    auto ldgA = [&](int kc) {
        const int k0 = kc * 32;
        #pragma unroll
        for (int r = 0; r < 4; r++) {
            int f = tid + r * 256;                 // 0..1023
            int row = f >> 3, kq = f & 7;
            areg[r] = *(const float4*)(A + (size_t)(m0 + row) * 256 + k0 + kq * 4);
        }
    };
    auto stsA = [&](uint32_t stage) {
        #pragma unroll
        for (int r = 0; r < 4; r++) {
            int f = tid + r * 256;
            int row = f >> 3, kq = f & 7;
            __nv_bfloat16 h0, h1, h2, h3, l0, l1, l2, l3;
            split_bf(areg[r].x, h0, l0);
            split_bf(areg[r].y, h1, l1);
            split_bf(areg[r].z, h2, l2);
            split_bf(areg[r].w, h3, l3);
            u32 so = SWZ64((u32)(row * 64 + kq * 8));
            *(uint2*)(sm + stage + so)          = make_uint2(pack2(h0, h1), pack2(h2, h3));
            *(uint2*)(sm + stage + OFF_AL + so) = make_uint2(pack2(l0, l1), pack2(l2, l3));
        }
    };
    auto cpaB = [&](int kc, uint32_t stage) {
        const int k0 = kc * 32;
        #pragma unroll
        for (int r = 0; r < 2; r++) {
            int f = tid + r * 256;                 // 0..511
            int row = f >> 2, kq = f & 3;          // row 0..127, 16B chunk 0..3
            u32 so = SWZ64((u32)(row * 64 + kq * 16));
            cpa16(sb + stage + OFF_BH + so,          Bh + (size_t)(n0 + row) * 256 + k0 + kq * 8);
            cpa16(sb + stage + OFF_BH + 8192u + so,  Bl + (size_t)(n0 + row) * 256 + k0 + kq * 8);
        }
        asm volatile("cp.async.commit_group;" ::: "memory");
    };

    float acc[4][4][4];
    #pragma unroll
    for (int mt = 0; mt < 4; mt++)
        #pragma unroll
        for (int nt = 0; nt < 4; nt++)
            #pragma unroll
            for (int x = 0; x < 4; x++) acc[mt][nt][x] = 0.f;

    auto compute = [&](uint32_t stage) {
        const uint32_t sA = sb + stage;
        const uint32_t sB = sb + stage + OFF_BH;
        #pragma unroll
        for (int ks = 0; ks < 2; ks++) {
            u32 Ah[4][4], Al[4][4];
            #pragma unroll
            for (int mt = 0; mt < 4; mt++) {
                u32 off = SWZ64((u32)((Wm0 + mt * 16 + am) * 64 + (ks * 2 + aq) * 16));
                ldsm4(Ah[mt], sA + off);
                ldsm4(Al[mt], sA + OFF_AL + off);
            }
            #pragma unroll
            for (int np = 0; np < 2; np++) {
                u32 offb = SWZ64((u32)((Wn0 + np * 16 + bn) * 64 + (ks * 2 + bq) * 16));
                u32 Bh4[4], Bl4[4];
                ldsm4(Bh4, sB + offb);
                ldsm4(Bl4, sB + 8192u + offb);
                #pragma unroll
                for (int mt = 0; mt < 4; mt++) {
                    mma16(acc[mt][2 * np],     Ah[mt], Bh4[0], Bh4[1]);
                    mma16(acc[mt][2 * np + 1], Ah[mt], Bh4[2], Bh4[3]);
                    mma16(acc[mt][2 * np],     Ah[mt], Bl4[0], Bl4[1]);
                    mma16(acc[mt][2 * np + 1], Ah[mt], Bl4[2], Bl4[3]);
                    mma16(acc[mt][2 * np],     Al[mt], Bh4[0], Bh4[1]);
                    mma16(acc[mt][2 * np + 1], Al[mt], Bh4[2], Bh4[3]);
                }
            }
        }
    };

    // ---- prologue: fill stages 0,1 ----
    ldgA(0); cpaB(0, 0);        stsA(0);
    ldgA(1); cpaB(1, STG);      stsA(STG);

    // ---- main loop ----
    for (int kc = 0; kc < NKC; kc++) {
        const uint32_t cur = (u32)(kc % 3) * STG;
        if (kc + 2 < NKC) ldgA(kc + 2);
        if (kc < NKC - 2) asm volatile("cp.async.wait_group 1;" ::: "memory");
        else              asm volatile("cp.async.wait_group 0;" ::: "memory");
        __syncthreads();
        if (kc + 2 < NKC) {
            const uint32_t nxt = (u32)((kc + 2) % 3) * STG;
            cpaB(kc + 2, nxt);
            stsA(nxt);
        }
        compute(cur);
    }

    // ---- epilogue ----
    #pragma unroll
    for (int mt = 0; mt < 4; mt++) {
        const int r0 = m0 + Wm0 + mt * 16 + (l >> 2);
        #pragma unroll
        for (int nt = 0; nt < 4; nt++) {
            const int col = Wn0 + nt * 8 + 2 * (l & 3);
            const float b0 = sbias[col], b1 = sbias[col + 1];
            float2 v0, v1;
            v0.x = fmaxf(acc[mt][nt][0] + b0, 0.f);
            v0.y = fmaxf(acc[mt][nt][1] + b1, 0.f);
            v1.x = fmaxf(acc[mt][nt][2] + b0, 0.f);
            v1.y = fmaxf(acc[mt][nt][3] + b1, 0.f);
            *(float2*)(C + (size_t)r0 * 256 + n0 + col)       = v0;
            *(float2*)(C + (size_t)(r0 + 8) * 256 + n0 + col) = v1;
        }
    }
}

// ---------------------------------------------------------------------------
// cv = (relu_c @ wc2)  — one warp per row, shuffle reduce.
// ---------------------------------------------------------------------------
__global__ __launch_bounds__(256)
void colvec_k(const float* __restrict__ A, const float* __restrict__ w,
              float* __restrict__ cv)
{
    const int row  = blockIdx.x * 8 + (threadIdx.x >> 5);
    const int lane = threadIdx.x & 31;
    const float* ar = A + (size_t)row * ND;
    float s = 0.f;
    #pragma unroll
    for (int c = lane; c < ND; c += 32) s += ar[c] * w[c];
    #pragma unroll
    for (int o = 16; o; o >>= 1) s += __shfl_xor_sync(0xffffffffu, s, o);
    if (lane == 0) cv[row] = s;
}

// ---------------------------------------------------------------------------
// Fused attention per batch (unchanged — known correct).
// ---------------------------------------------------------------------------
#define QS 257
#define SMF (2 * NT * QS + NT * ND + NT * 65 + NT + NT * 3)
#define ATTN_SMEM (SMF * 4)

__global__ __launch_bounds__(256, 1)
void attn_k(const float* __restrict__ q, const float* __restrict__ k,
            const float* __restrict__ v, const float* __restrict__ cv,
            const float* __restrict__ h, const float* __restrict__ coord,
            float* __restrict__ outh, float* __restrict__ outx)
{
    extern __shared__ float smf[];
    float* sq  = smf;                   // 64 x 257
    float* sk  = sq + NT * QS;          // 64 x 257
    float* sv  = sk + NT * QS;          // 64 x 256
    float* ss  = sv + NT * ND;          // 64 x 65
    float* scv = ss + NT * 65;          // 64
    float* sco = scv + NT;              // 64 x 3

    const int b = blockIdx.x, tid = threadIdx.x;
    const size_t base = (size_t)b * (NT * ND);

    for (int idx = tid; idx < NT * ND; idx += 256) {
        int r = idx >> 8, c = idx & 255;
        sq[r * QS + c] = q[base + idx];
        sk[r * QS + c] = k[base + idx];
        sv[idx]        = v[base + idx];
    }
    if (tid < NT)      scv[tid] = cv[(size_t)b * NT + tid];
    if (tid < NT * 3)  sco[tid] = coord[(size_t)b * (NT * 3) + tid];
    __syncthreads();

    {
        const int i0 = (tid >> 4) * 4, j0 = (tid & 15) * 4;
        float acc[4][4] = {};
        for (int d = 0; d < ND; d++) {
            float qa[4], kb[4];
            #pragma unroll
            for (int ii = 0; ii < 4; ii++) qa[ii] = sq[(i0 + ii) * QS + d];
            #pragma unroll
            for (int jj = 0; jj < 4; jj++) kb[jj] = sk[(j0 + jj) * QS + d];
            #pragma unroll
            for (int ii = 0; ii < 4; ii++)
                #pragma unroll
                for (int jj = 0; jj < 4; jj++) acc[ii][jj] += qa[ii] * kb[jj];
        }
        #pragma unroll
        for (int ii = 0; ii < 4; ii++)
            #pragma unroll
            for (int jj = 0; jj < 4; jj++)
                ss[(i0 + ii) * 65 + j0 + jj] = acc[ii][jj];
    }
    __syncthreads();

    if (tid < NT) {
        const int i = tid;
        float m = -1e30f;
        for (int j = 0; j < NT; j++) m = fmaxf(m, ss[i * 65 + j]);
        float sum = 0.f;
        for (int j = 0; j < NT; j++) {
            float e = expf(ss[i * 65 + j] - m);
            ss[i * 65 + j] = e;
            sum += e;
        }
        float inv = 1.f / sum;
        float wsum = 0.f, w0 = 0.f, w1 = 0.f, w2 = 0.f;
        for (int j = 0; j < NT; j++) {
            float a = ss[i * 65 + j] * inv;
            ss[i * 65 + j] = a;
            float wv = a * scv[j];
            wsum += wv;
            w0 += wv * sco[j * 3 + 0];
            w1 += wv * sco[j * 3 + 1];
            w2 += wv * sco[j * 3 + 2];
        }
        size_t ob = (size_t)b * (NT * 3) + i * 3;
        outx[ob + 0] = sco[i * 3 + 0] + w0 - sco[i * 3 + 0] * wsum;
        outx[ob + 1] = sco[i * 3 + 1] + w1 - sco[i * 3 + 1] * wsum;
        outx[ob + 2] = sco[i * 3 + 2] + w2 - sco[i * 3 + 2] * wsum;
    }
    __syncthreads();

    {
        const int i0 = (tid >> 4) * 4, d0 = (tid & 15) * 16;
        float hacc[4][16] = {};
        for (int j = 0; j < NT; j++) {
            float a[4];
            #pragma unroll
            for (int ii = 0; ii < 4; ii++) a[ii] = ss[(i0 + ii) * 65 + j];
            const float* vr = &sv[j * ND + d0];
            #pragma unroll
            for (int dq = 0; dq < 4; dq++) {
                float4 vv = *(const float4*)(vr + dq * 4);
                #pragma unroll
                for (int ii = 0; ii < 4; ii++) {
                    hacc[ii][dq * 4 + 0] += a[ii] * vv.x;
                    hacc[ii][dq * 4 + 1] += a[ii] * vv.y;
                    hacc[ii][dq * 4 + 2] += a[ii] * vv.z;
                    hacc[ii][dq * 4 + 3] += a[ii] * vv.w;
                }
            }
        }
        #pragma unroll
        for (int ii = 0; ii < 4; ii++) {
            const size_t o = base + (size_t)(i0 + ii) * ND + d0;
            #pragma unroll
            for (int dq = 0; dq < 4; dq++) {
                float4 hv = *(const float4*)(h + o + dq * 4);
                float4 r  = make_float4(hv.x + hacc[ii][dq * 4 + 0],
                                        hv.y + hacc[ii][dq * 4 + 1],
                                        hv.z + hacc[ii][dq * 4 + 2],
                                        hv.w + hacc[ii][dq * 4 + 3]);
                *(float4*)(outh + o + dq * 4) = r;
            }
        }
    }
}

// ---------------------------------------------------------------------------
extern "C" void kernel_launch(void* const* d_in, const int* in_sizes, int n_in,
                              void* d_out, int out_size)
{
    (void)in_sizes; (void)n_in; (void)out_size;
    const float* h     = (const float*)d_in[0];
    const float* coord = (const float*)d_in[1];
    const float* Wq1 = (const float*)d_in[2];
    const float* bq1 = (const float*)d_in[3];
    const float* Wq2 = (const float*)d_in[4];
    const float* bq2 = (const float*)d_in[5];
    const float* Wk1 = (const float*)d_in[6];
    const float* bk1 = (const float*)d_in[7];
    const float* Wk2 = (const float*)d_in[8];
    const float* bk2 = (const float*)d_in[9];
    const float* Wv1 = (const float*)d_in[10];
    const float* bv1 = (const float*)d_in[11];
    const float* Wv2 = (const float*)d_in[12];
    const float* bv2 = (const float*)d_in[13];
    const float* Wc1 = (const float*)d_in[14];
    const float* bc1 = (const float*)d_in[15];
    const float* wc2 = (const float*)d_in[16];

    float* out_h = (float*)d_out;
    float* out_x = out_h + (size_t)BT * ND;

    float *tmp, *q, *k, *v, *cv;
    __nv_bfloat16 *wbh, *wbl;
    cudaGetSymbolAddress((void**)&tmp, g_tmp);
    cudaGetSymbolAddress((void**)&q,   g_q);
    cudaGetSymbolAddress((void**)&k,   g_k);
    cudaGetSymbolAddress((void**)&v,   g_v);
    cudaGetSymbolAddress((void**)&cv,  g_cv);
    cudaGetSymbolAddress((void**)&wbh, g_wbh);
    cudaGetSymbolAddress((void**)&wbl, g_wbl);

    const float* Ws[7] = {Wq1, Wq2, Wk1, Wk2, Wv1, Wv2, Wc1};
    for (int i = 0; i < 7; i++)
        prep_w<<<256, 256>>>(Ws[i], wbh + (size_t)i * ND * ND, wbl + (size_t)i * ND * ND);

    cudaFuncSetAttribute(gemm_mma, cudaFuncAttributeMaxDynamicSharedMemorySize, GEMM_SMEM);
    #define WH(i) (wbh + (size_t)(i) * ND * ND)
    #define WL(i) (wbl + (size_t)(i) * ND * ND)

    dim3 gg(2048, 2);
    gemm_mma<<<gg, 256, GEMM_SMEM>>>(h,   WH(0), WL(0), bq1, tmp);
    gemm_mma<<<gg, 256, GEMM_SMEM>>>(tmp, WH(1), WL(1), bq2, q);
    gemm_mma<<<gg, 256, GEMM_SMEM>>>(h,   WH(2), WL(2), bk1, tmp);
    gemm_mma<<<gg, 256, GEMM_SMEM>>>(tmp, WH(3), WL(3), bk2, k);
    gemm_mma<<<gg, 256, GEMM_SMEM>>>(h,   WH(4), WL(4), bv1, tmp);
    gemm_mma<<<gg, 256, GEMM_SMEM>>>(tmp, WH(5), WL(5), bv2, v);
    gemm_mma<<<gg, 256, GEMM_SMEM>>>(v,   WH(6), WL(6), bc1, tmp);
    colvec_k<<<BT / 8, 256>>>(tmp, wc2, cv);

    cudaFuncSetAttribute(attn_k, cudaFuncAttributeMaxDynamicSharedMemorySize, ATTN_SMEM);
    attn_k<<<NB, 256, ATTN_SMEM>>>(q, k, v, cv, h, coord, out_h, out_x);
}

// round 5
// speedup vs baseline: 2.0206x; 1.0337x over previous
#include <cuda_runtime.h>
#include <cuda_bf16.h>
#include <math.h>
#include <stdint.h>

typedef unsigned long long u64;
typedef unsigned int u32;

#define NB 4096
#define NT 64
#define ND 256
#define BT (NB * NT)          // 262144 rows

// ---------------- scratch (static device globals; no allocations) ----------
__device__ __nv_bfloat16 g_hh [(size_t)BT * ND];
__device__ __nv_bfloat16 g_hl [(size_t)BT * ND];
__device__ __nv_bfloat16 g_th [(size_t)BT * ND];
__device__ __nv_bfloat16 g_tl [(size_t)BT * ND];
__device__ __nv_bfloat16 g_qh [(size_t)BT * ND];
__device__ __nv_bfloat16 g_ql [(size_t)BT * ND];
__device__ __nv_bfloat16 g_kh [(size_t)BT * ND];
__device__ __nv_bfloat16 g_kl [(size_t)BT * ND];
__device__ __nv_bfloat16 g_vh [(size_t)BT * ND];
__device__ __nv_bfloat16 g_vl [(size_t)BT * ND];
__device__ float g_cv [(size_t)BT];
__device__ __nv_bfloat16 g_wbh[7][ND * ND];   // transposed bf16-hi weights [n][k]
__device__ __nv_bfloat16 g_wbl[7][ND * ND];   // transposed bf16-lo weights [n][k]

// ---------------------------------------------------------------------------
#define SWZ64(o) ((o) ^ (((o) >> 3) & 0x30))

__device__ __forceinline__ uint32_t s2u(const void* p) {
    uint32_t a;
    asm("{ .reg .u64 t; cvta.to.shared.u64 t, %1; cvt.u32.u64 %0, t; }" : "=r"(a) : "l"(p));
    return a;
}
__device__ __forceinline__ void cpa16(uint32_t dst, const void* src) {
    asm volatile("cp.async.cg.shared.global [%0], [%1], 16;" :: "r"(dst), "l"(src));
}
__device__ __forceinline__ void ldsm4(u32 r[4], uint32_t addr) {
    asm volatile("ldmatrix.sync.aligned.m8n8.x4.shared.b16 {%0,%1,%2,%3}, [%4];"
        : "=r"(r[0]), "=r"(r[1]), "=r"(r[2]), "=r"(r[3]) : "r"(addr));
}
__device__ __forceinline__ void mma16(float c[4], const u32 a[4], u32 b0, u32 b1) {
    asm volatile(
        "mma.sync.aligned.m16n8k16.row.col.f32.bf16.bf16.f32 "
        "{%0,%1,%2,%3}, {%4,%5,%6,%7}, {%8,%9}, {%0,%1,%2,%3};"
        : "+f"(c[0]), "+f"(c[1]), "+f"(c[2]), "+f"(c[3])
        : "r"(a[0]), "r"(a[1]), "r"(a[2]), "r"(a[3]), "r"(b0), "r"(b1));
}
__device__ __forceinline__ u32 pack2(__nv_bfloat16 a, __nv_bfloat16 b) {
    return (u32)__bfloat16_as_ushort(a) | ((u32)__bfloat16_as_ushort(b) << 16);
}
__device__ __forceinline__ void split_bf(float x, __nv_bfloat16& hi, __nv_bfloat16& lo) {
    hi = __float2bfloat16_rn(x);
    lo = __float2bfloat16_rn(x - __bfloat162float(hi));
}
__device__ __forceinline__ float2 rec2(u32 h2, u32 l2) {
    __nv_bfloat162 hb = *(__nv_bfloat162*)&h2;
    __nv_bfloat162 lb = *(__nv_bfloat162*)&l2;
    float2 hf = __bfloat1622float2(hb);
    float2 lf = __bfloat1622float2(lb);
    return make_float2(hf.x + lf.x, hf.y + lf.y);
}

// ---------------------------------------------------------------------------
// prep_w: bf16 hi/lo split of W, transposed to [n][k]
// ---------------------------------------------------------------------------
__global__ __launch_bounds__(256)
void prep_w(const float* __restrict__ W, __nv_bfloat16* __restrict__ Bh,
            __nv_bfloat16* __restrict__ Bl)
{
    int idx = blockIdx.x * 256 + threadIdx.x;   // 0..65535
    int k = idx >> 8, n = idx & 255;
    float w = W[idx];
    __nv_bfloat16 hi, lo;
    split_bf(w, hi, lo);
    Bh[n * 256 + k] = hi;
    Bl[n * 256 + k] = lo;
}

// ---------------------------------------------------------------------------
// prep_h: split fp32 activations into bf16 hi/lo arrays (vectorized).
// ---------------------------------------------------------------------------
__global__ __launch_bounds__(256)
void prep_h(const float* __restrict__ H, __nv_bfloat16* __restrict__ Hh,
            __nv_bfloat16* __restrict__ Hl)
{
    size_t i = ((size_t)blockIdx.x * 256 + threadIdx.x) * 4;
    float4 v = *(const float4*)(H + i);
    __nv_bfloat16 h0, h1, h2, h3, l0, l1, l2, l3;
    split_bf(v.x, h0, l0);
    split_bf(v.y, h1, l1);
    split_bf(v.z, h2, l2);
    split_bf(v.w, h3, l3);
    *(uint2*)(Hh + i) = make_uint2(pack2(h0, h1), pack2(h2, h3));
    *(uint2*)(Hl + i) = make_uint2(pack2(l0, l1), pack2(l2, l3));
}

// ---------------------------------------------------------------------------
// gemm_mma: Chi/Clo = split(relu(A @ W + bias)), bf16x3 mma.sync.
// A given as pre-split hi/lo bf16. CTA 128x128, 8 warps (warp 64x32),
// k-chunk 32, 3-stage pure-cp.async pipeline, occ=2. Grid (2, 2048):
// n-block CTAs of same m adjacent -> A read hits L2 on second block.
// Stage (32KB): Ahi[0,8K) Alo[8K,16K) Bhi[16K,24K) Blo[24K,32K)
// ---------------------------------------------------------------------------
#define STG   32768u
#define OFF_AL 8192u
#define OFF_BH 16384u
#define OFF_BIAS (3 * 32768)
#define GEMM_SMEM (3 * 32768 + 512)
#define NKC 8

__global__ __launch_bounds__(256, 2)
void gemm_mma(const __nv_bfloat16* __restrict__ Ah_g, const __nv_bfloat16* __restrict__ Al_g,
              const __nv_bfloat16* __restrict__ Bh_g, const __nv_bfloat16* __restrict__ Bl_g,
              const float* __restrict__ bias,
              __nv_bfloat16* __restrict__ Chi, __nv_bfloat16* __restrict__ Clo)
{
    extern __shared__ char sm[];
    const uint32_t sb = s2u(sm);
    float* sbias = (float*)(sm + OFF_BIAS);
    const int tid = threadIdx.x, wid = tid >> 5, l = tid & 31;
    const int n0 = blockIdx.x * 128;
    const int m0 = blockIdx.y * 128;

    const int Wm0 = (wid & 1) * 64;
    const int Wn0 = (wid >> 1) * 32;
    const int am = l & 15, aq = l >> 4;
    const int bn = (l & 7) + ((l >> 4) << 3), bq = (l >> 3) & 1;

    if (tid < 128) sbias[tid] = bias[n0 + tid];

    auto cpAB = [&](int kc, uint32_t stage) {
        const int k0 = kc * 32;
        #pragma unroll
        for (int r = 0; r < 2; r++) {
            int f = tid + r * 256;                 // 0..511
            int row = f >> 2, kq = f & 3;          // row 0..127, 16B chunk 0..3
            u32 so = SWZ64((u32)(row * 64 + kq * 16));
            const size_t asrc = (size_t)(m0 + row) * 256 + k0 + kq * 8;
            const size_t bsrc = (size_t)(n0 + row) * 256 + k0 + kq * 8;
            cpa16(sb + stage + so,            Ah_g + asrc);
            cpa16(sb + stage + OFF_AL + so,   Al_g + asrc);
            cpa16(sb + stage + OFF_BH + so,   Bh_g + bsrc);
            cpa16(sb + stage + OFF_BH + 8192u + so, Bl_g + bsrc);
        }
        asm volatile("cp.async.commit_group;" ::: "memory");
    };

    float acc[4][4][4];
    #pragma unroll
    for (int mt = 0; mt < 4; mt++)
        #pragma unroll
        for (int nt = 0; nt < 4; nt++)
            #pragma unroll
            for (int x = 0; x < 4; x++) acc[mt][nt][x] = 0.f;

    auto compute = [&](uint32_t stage) {
        const uint32_t sA = sb + stage;
        const uint32_t sB = sb + stage + OFF_BH;
        #pragma unroll
        for (int ks = 0; ks < 2; ks++) {
            u32 Ah[4][4], Al[4][4];
            #pragma unroll
            for (int mt = 0; mt < 4; mt++) {
                u32 off = SWZ64((u32)((Wm0 + mt * 16 + am) * 64 + (ks * 2 + aq) * 16));
                ldsm4(Ah[mt], sA + off);
                ldsm4(Al[mt], sA + OFF_AL + off);
            }
            #pragma unroll
            for (int np = 0; np < 2; np++) {
                u32 offb = SWZ64((u32)((Wn0 + np * 16 + bn) * 64 + (ks * 2 + bq) * 16));
                u32 Bh4[4], Bl4[4];
                ldsm4(Bh4, sB + offb);
                ldsm4(Bl4, sB + 8192u + offb);
                #pragma unroll
                for (int mt = 0; mt < 4; mt++) {
                    mma16(acc[mt][2 * np],     Ah[mt], Bh4[0], Bh4[1]);
                    mma16(acc[mt][2 * np + 1], Ah[mt], Bh4[2], Bh4[3]);
                    mma16(acc[mt][2 * np],     Ah[mt], Bl4[0], Bl4[1]);
                    mma16(acc[mt][2 * np + 1], Ah[mt], Bl4[2], Bl4[3]);
                    mma16(acc[mt][2 * np],     Al[mt], Bh4[0], Bh4[1]);
                    mma16(acc[mt][2 * np + 1], Al[mt], Bh4[2], Bh4[3]);
                }
            }
        }
    };

    // ---- prologue: fill stages 0,1 ----
    cpAB(0, 0);
    cpAB(1, STG);

    // ---- main loop ----
    for (int kc = 0; kc < NKC; kc++) {
        const uint32_t cur = (u32)(kc % 3) * STG;
        if (kc < NKC - 2) asm volatile("cp.async.wait_group 1;" ::: "memory");
        else              asm volatile("cp.async.wait_group 0;" ::: "memory");
        __syncthreads();
        if (kc + 2 < NKC) cpAB(kc + 2, (u32)((kc + 2) % 3) * STG);
        compute(cur);
    }

    // ---- epilogue: bias + relu + split, write Chi/Clo ----
    #pragma unroll
    for (int mt = 0; mt < 4; mt++) {
        const int r0 = m0 + Wm0 + mt * 16 + (l >> 2);
        #pragma unroll
        for (int nt = 0; nt < 4; nt++) {
            const int col = n0 + Wn0 + nt * 8 + 2 * (l & 3);
            const float b0 = sbias[col - n0], b1 = sbias[col - n0 + 1];
            float x0 = fmaxf(acc[mt][nt][0] + b0, 0.f);
            float x1 = fmaxf(acc[mt][nt][1] + b1, 0.f);
            float x2 = fmaxf(acc[mt][nt][2] + b0, 0.f);
            float x3 = fmaxf(acc[mt][nt][3] + b1, 0.f);
            __nv_bfloat16 h0, h1, h2, h3, l0x, l1x, l2x, l3x;
            split_bf(x0, h0, l0x); split_bf(x1, h1, l1x);
            split_bf(x2, h2, l2x); split_bf(x3, h3, l3x);
            *(u32*)(Chi + (size_t)r0 * 256 + col)       = pack2(h0, h1);
            *(u32*)(Clo + (size_t)r0 * 256 + col)       = pack2(l0x, l1x);
            *(u32*)(Chi + (size_t)(r0 + 8) * 256 + col) = pack2(h2, h3);
            *(u32*)(Clo + (size_t)(r0 + 8) * 256 + col) = pack2(l2x, l3x);
        }
    }
}

// ---------------------------------------------------------------------------
// cv = (relu_c @ wc2) — A given as hi/lo bf16; one warp per row.
// ---------------------------------------------------------------------------
__global__ __launch_bounds__(256)
void colvec_k(const __nv_bfloat16* __restrict__ Ahi, const __nv_bfloat16* __restrict__ Alo,
              const float* __restrict__ w, float* __restrict__ cv)
{
    const int row  = blockIdx.x * 8 + (threadIdx.x >> 5);
    const int lane = threadIdx.x & 31;
    const u32* ah = (const u32*)(Ahi + (size_t)row * ND);
    const u32* al = (const u32*)(Alo + (size_t)row * ND);
    float s = 0.f;
    #pragma unroll
    for (int it = 0; it < 4; it++) {
        int c2 = lane + it * 32;                 // u32 index (2 elems)
        float2 a = rec2(ah[c2], al[c2]);
        float2 wv = *(const float2*)(w + c2 * 2);
        s += a.x * wv.x + a.y * wv.y;
    }
    #pragma unroll
    for (int o = 16; o; o >>= 1) s += __shfl_xor_sync(0xffffffffu, s, o);
    if (lane == 0) cv[row] = s;
}

// ---------------------------------------------------------------------------
// Fused attention per batch. q/k/v arrive as bf16 hi/lo; reconstructed on load.
// ---------------------------------------------------------------------------
#define QS 257
#define SMF (2 * NT * QS + NT * ND + NT * 65 + NT + NT * 3)
#define ATTN_SMEM (SMF * 4)

__global__ __launch_bounds__(256, 1)
void attn_k(const __nv_bfloat16* __restrict__ qh, const __nv_bfloat16* __restrict__ ql,
            const __nv_bfloat16* __restrict__ kh, const __nv_bfloat16* __restrict__ kl,
            const __nv_bfloat16* __restrict__ vh, const __nv_bfloat16* __restrict__ vl,
            const float* __restrict__ cv,
            const float* __restrict__ h, const float* __restrict__ coord,
            float* __restrict__ outh, float* __restrict__ outx)
{
    extern __shared__ float smf[];
    float* sq  = smf;                   // 64 x 257
    float* sk  = sq + NT * QS;          // 64 x 257
    float* sv  = sk + NT * QS;          // 64 x 256
    float* ss  = sv + NT * ND;          // 64 x 65
    float* scv = ss + NT * 65;          // 64
    float* sco = scv + NT;              // 64 x 3

    const int b = blockIdx.x, tid = threadIdx.x;
    const size_t base  = (size_t)b * (NT * ND);
    const size_t base2 = base >> 1;

    const u32* qh2 = (const u32*)qh; const u32* ql2 = (const u32*)ql;
    const u32* kh2 = (const u32*)kh; const u32* kl2 = (const u32*)kl;
    const u32* vh2 = (const u32*)vh; const u32* vl2 = (const u32*)vl;

    for (int idx = tid; idx < NT * ND / 2; idx += 256) {
        int r = idx >> 7, c = idx & 127;
        float2 qv = rec2(qh2[base2 + idx], ql2[base2 + idx]);
        float2 kv = rec2(kh2[base2 + idx], kl2[base2 + idx]);
        float2 vv = rec2(vh2[base2 + idx], vl2[base2 + idx]);
        sq[r * QS + 2 * c]     = qv.x;
        sq[r * QS + 2 * c + 1] = qv.y;
        sk[r * QS + 2 * c]     = kv.x;
        sk[r * QS + 2 * c + 1] = kv.y;
        sv[r * 256 + 2 * c]     = vv.x;
        sv[r * 256 + 2 * c + 1] = vv.y;
    }
    if (tid < NT)      scv[tid] = cv[(size_t)b * NT + tid];
    if (tid < NT * 3)  sco[tid] = coord[(size_t)b * (NT * 3) + tid];
    __syncthreads();

    {
        const int i0 = (tid >> 4) * 4, j0 = (tid & 15) * 4;
        float acc[4][4] = {};
        for (int d = 0; d < ND; d++) {
            float qa[4], kb[4];
            #pragma unroll
            for (int ii = 0; ii < 4; ii++) qa[ii] = sq[(i0 + ii) * QS + d];
            #pragma unroll
            for (int jj = 0; jj < 4; jj++) kb[jj] = sk[(j0 + jj) * QS + d];
            #pragma unroll
            for (int ii = 0; ii < 4; ii++)
                #pragma unroll
                for (int jj = 0; jj < 4; jj++) acc[ii][jj] += qa[ii] * kb[jj];
        }
        #pragma unroll
        for (int ii = 0; ii < 4; ii++)
            #pragma unroll
            for (int jj = 0; jj < 4; jj++)
                ss[(i0 + ii) * 65 + j0 + jj] = acc[ii][jj];
    }
    __syncthreads();

    if (tid < NT) {
        const int i = tid;
        float m = -1e30f;
        for (int j = 0; j < NT; j++) m = fmaxf(m, ss[i * 65 + j]);
        float sum = 0.f;
        for (int j = 0; j < NT; j++) {
            float e = expf(ss[i * 65 + j] - m);
            ss[i * 65 + j] = e;
            sum += e;
        }
        float inv = 1.f / sum;
        float wsum = 0.f, w0 = 0.f, w1 = 0.f, w2 = 0.f;
        for (int j = 0; j < NT; j++) {
            float a = ss[i * 65 + j] * inv;
            ss[i * 65 + j] = a;
            float wv = a * scv[j];
            wsum += wv;
            w0 += wv * sco[j * 3 + 0];
            w1 += wv * sco[j * 3 + 1];
            w2 += wv * sco[j * 3 + 2];
        }
        size_t ob = (size_t)b * (NT * 3) + i * 3;
        outx[ob + 0] = sco[i * 3 + 0] + w0 - sco[i * 3 + 0] * wsum;
        outx[ob + 1] = sco[i * 3 + 1] + w1 - sco[i * 3 + 1] * wsum;
        outx[ob + 2] = sco[i * 3 + 2] + w2 - sco[i * 3 + 2] * wsum;
    }
    __syncthreads();

    {
        const int i0 = (tid >> 4) * 4, d0 = (tid & 15) * 16;
        float hacc[4][16] = {};
        for (int j = 0; j < NT; j++) {
            float a[4];
            #pragma unroll
            for (int ii = 0; ii < 4; ii++) a[ii] = ss[(i0 + ii) * 65 + j];
            const float* vr = &sv[j * ND + d0];
            #pragma unroll
            for (int dq = 0; dq < 4; dq++) {
                float4 vv = *(const float4*)(vr + dq * 4);
                #pragma unroll
                for (int ii = 0; ii < 4; ii++) {
                    hacc[ii][dq * 4 + 0] += a[ii] * vv.x;
                    hacc[ii][dq * 4 + 1] += a[ii] * vv.y;
                    hacc[ii][dq * 4 + 2] += a[ii] * vv.z;
                    hacc[ii][dq * 4 + 3] += a[ii] * vv.w;
                }
            }
        }
        #pragma unroll
        for (int ii = 0; ii < 4; ii++) {
            const size_t o = base + (size_t)(i0 + ii) * ND + d0;
            #pragma unroll
            for (int dq = 0; dq < 4; dq++) {
                float4 hv = *(const float4*)(h + o + dq * 4);
                float4 r  = make_float4(hv.x + hacc[ii][dq * 4 + 0],
                                        hv.y + hacc[ii][dq * 4 + 1],
                                        hv.z + hacc[ii][dq * 4 + 2],
                                        hv.w + hacc[ii][dq * 4 + 3]);
                *(float4*)(outh + o + dq * 4) = r;
            }
        }
    }
}

// ---------------------------------------------------------------------------
extern "C" void kernel_launch(void* const* d_in, const int* in_sizes, int n_in,
                              void* d_out, int out_size)
{
    (void)in_sizes; (void)n_in; (void)out_size;
    const float* h     = (const float*)d_in[0];
    const float* coord = (const float*)d_in[1];
    const float* Wq1 = (const float*)d_in[2];
    const float* bq1 = (const float*)d_in[3];
    const float* Wq2 = (const float*)d_in[4];
    const float* bq2 = (const float*)d_in[5];
    const float* Wk1 = (const float*)d_in[6];
    const float* bk1 = (const float*)d_in[7];
    const float* Wk2 = (const float*)d_in[8];
    const float* bk2 = (const float*)d_in[9];
    const float* Wv1 = (const float*)d_in[10];
    const float* bv1 = (const float*)d_in[11];
    const float* Wv2 = (const float*)d_in[12];
    const float* bv2 = (const float*)d_in[13];
    const float* Wc1 = (const float*)d_in[14];
    const float* bc1 = (const float*)d_in[15];
    const float* wc2 = (const float*)d_in[16];

    float* out_h = (float*)d_out;
    float* out_x = out_h + (size_t)BT * ND;

    __nv_bfloat16 *hh, *hl, *th, *tl, *qh, *ql, *kh, *kl, *vh, *vl, *wbh, *wbl;
    float *cv;
    cudaGetSymbolAddress((void**)&hh, g_hh);  cudaGetSymbolAddress((void**)&hl, g_hl);
    cudaGetSymbolAddress((void**)&th, g_th);  cudaGetSymbolAddress((void**)&tl, g_tl);
    cudaGetSymbolAddress((void**)&qh, g_qh);  cudaGetSymbolAddress((void**)&ql, g_ql);
    cudaGetSymbolAddress((void**)&kh, g_kh);  cudaGetSymbolAddress((void**)&kl, g_kl);
    cudaGetSymbolAddress((void**)&vh, g_vh);  cudaGetSymbolAddress((void**)&vl, g_vl);
    cudaGetSymbolAddress((void**)&cv, g_cv);
    cudaGetSymbolAddress((void**)&wbh, g_wbh);
    cudaGetSymbolAddress((void**)&wbl, g_wbl);

    const float* Ws[7] = {Wq1, Wq2, Wk1, Wk2, Wv1, Wv2, Wc1};
    for (int i = 0; i < 7; i++)
        prep_w<<<256, 256>>>(Ws[i], wbh + (size_t)i * ND * ND, wbl + (size_t)i * ND * ND);
    prep_h<<<BT * ND / 1024, 256>>>(h, hh, hl);

    cudaFuncSetAttribute(gemm_mma, cudaFuncAttributeMaxDynamicSharedMemorySize, GEMM_SMEM);
    #define WH(i) (wbh + (size_t)(i) * ND * ND)
    #define WL(i) (wbl + (size_t)(i) * ND * ND)

    dim3 gg(2, 2048);
    gemm_mma<<<gg, 256, GEMM_SMEM>>>(hh, hl, WH(0), WL(0), bq1, th, tl);
    gemm_mma<<<gg, 256, GEMM_SMEM>>>(th, tl, WH(1), WL(1), bq2, qh, ql);
    gemm_mma<<<gg, 256, GEMM_SMEM>>>(hh, hl, WH(2), WL(2), bk1, th, tl);
    gemm_mma<<<gg, 256, GEMM_SMEM>>>(th, tl, WH(3), WL(3), bk2, kh, kl);
    gemm_mma<<<gg, 256, GEMM_SMEM>>>(hh, hl, WH(4), WL(4), bv1, th, tl);
    gemm_mma<<<gg, 256, GEMM_SMEM>>>(th, tl, WH(5), WL(5), bv2, vh, vl);
    gemm_mma<<<gg, 256, GEMM_SMEM>>>(vh, vl, WH(6), WL(6), bc1, th, tl);
    colvec_k<<<BT / 8, 256>>>(th, tl, wc2, cv);

    cudaFuncSetAttribute(attn_k, cudaFuncAttributeMaxDynamicSharedMemorySize, ATTN_SMEM);
    attn_k<<<NB, 256, ATTN_SMEM>>>(qh, ql, kh, kl, vh, vl, cv, h, coord, out_h, out_x);
}

// round 8
// speedup vs baseline: 2.0892x; 1.0340x over previous
#include <cuda_runtime.h>
#include <cuda_bf16.h>
#include <math.h>
#include <stdint.h>

typedef unsigned long long u64;
typedef unsigned int u32;

#define NB 4096
#define NT 64
#define ND 256
#define BT (NB * NT)          // 262144 rows

// ---------------- scratch (static device globals; no allocations) ----------
__device__ __nv_bfloat16 g_hh [(size_t)BT * ND];
__device__ __nv_bfloat16 g_hl [(size_t)BT * ND];
__device__ __nv_bfloat16 g_th [(size_t)BT * ND];
__device__ __nv_bfloat16 g_tl [(size_t)BT * ND];
__device__ __nv_bfloat16 g_qh [(size_t)BT * ND];
__device__ __nv_bfloat16 g_ql [(size_t)BT * ND];
__device__ __nv_bfloat16 g_kh [(size_t)BT * ND];
__device__ __nv_bfloat16 g_kl [(size_t)BT * ND];
__device__ __nv_bfloat16 g_vh [(size_t)BT * ND];
__device__ __nv_bfloat16 g_vl [(size_t)BT * ND];
__device__ float g_cv [(size_t)BT];
__device__ __nv_bfloat16 g_wbh[7][ND * ND];   // transposed bf16-hi weights [n][k]
__device__ __nv_bfloat16 g_wbl[7][ND * ND];   // transposed bf16-lo weights [n][k]

// ---------------------------------------------------------------------------
#define SWZ64(o) ((o) ^ (((o) >> 3) & 0x30))

__device__ __forceinline__ uint32_t s2u(const void* p) {
    uint32_t a;
    asm("{ .reg .u64 t; cvta.to.shared.u64 t, %1; cvt.u32.u64 %0, t; }" : "=r"(a) : "l"(p));
    return a;
}
__device__ __forceinline__ void cpa16(uint32_t dst, const void* src) {
    asm volatile("cp.async.cg.shared.global [%0], [%1], 16;" :: "r"(dst), "l"(src));
}
__device__ __forceinline__ void ldsm4(u32 r[4], uint32_t addr) {
    asm volatile("ldmatrix.sync.aligned.m8n8.x4.shared.b16 {%0,%1,%2,%3}, [%4];"
        : "=r"(r[0]), "=r"(r[1]), "=r"(r[2]), "=r"(r[3]) : "r"(addr));
}
__device__ __forceinline__ void mma16(float c[4], const u32 a[4], u32 b0, u32 b1) {
    asm volatile(
        "mma.sync.aligned.m16n8k16.row.col.f32.bf16.bf16.f32 "
        "{%0,%1,%2,%3}, {%4,%5,%6,%7}, {%8,%9}, {%0,%1,%2,%3};"
        : "+f"(c[0]), "+f"(c[1]), "+f"(c[2]), "+f"(c[3])
        : "r"(a[0]), "r"(a[1]), "r"(a[2]), "r"(a[3]), "r"(b0), "r"(b1));
}
__device__ __forceinline__ u32 pack2(__nv_bfloat16 a, __nv_bfloat16 b) {
    return (u32)__bfloat16_as_ushort(a) | ((u32)__bfloat16_as_ushort(b) << 16);
}
__device__ __forceinline__ void split_bf(float x, __nv_bfloat16& hi, __nv_bfloat16& lo) {
    hi = __float2bfloat16_rn(x);
    lo = __float2bfloat16_rn(x - __bfloat162float(hi));
}
__device__ __forceinline__ float2 rec2(u32 h2, u32 l2) {
    __nv_bfloat162 hb = *(__nv_bfloat162*)&h2;
    __nv_bfloat162 lb = *(__nv_bfloat162*)&l2;
    float2 hf = __bfloat1622float2(hb);
    float2 lf = __bfloat1622float2(lb);
    return make_float2(hf.x + lf.x, hf.y + lf.y);
}

// ---------------------------------------------------------------------------
// prep_w / prep_h
// ---------------------------------------------------------------------------
__global__ __launch_bounds__(256)
void prep_w(const float* __restrict__ W, __nv_bfloat16* __restrict__ Bh,
            __nv_bfloat16* __restrict__ Bl)
{
    int idx = blockIdx.x * 256 + threadIdx.x;   // 0..65535
    int k = idx >> 8, n = idx & 255;
    float w = W[idx];
    __nv_bfloat16 hi, lo;
    split_bf(w, hi, lo);
    Bh[n * 256 + k] = hi;
    Bl[n * 256 + k] = lo;
}

__global__ __launch_bounds__(256)
void prep_h(const float* __restrict__ H, __nv_bfloat16* __restrict__ Hh,
            __nv_bfloat16* __restrict__ Hl)
{
    size_t i = ((size_t)blockIdx.x * 256 + threadIdx.x) * 4;
    float4 v = *(const float4*)(H + i);
    __nv_bfloat16 h0, h1, h2, h3, l0, l1, l2, l3;
    split_bf(v.x, h0, l0);
    split_bf(v.y, h1, l1);
    split_bf(v.z, h2, l2);
    split_bf(v.w, h3, l3);
    *(uint2*)(Hh + i) = make_uint2(pack2(h0, h1), pack2(h2, h3));
    *(uint2*)(Hl + i) = make_uint2(pack2(l0, l1), pack2(l2, l3));
}

// ---------------------------------------------------------------------------
// gemm_mma<FULL>: Chi/Clo = split(relu(A @ W + bias)).
// FULL=true : bf16x3 (Ah·Bh + Ah·Bl + Al·Bh)
// FULL=false: single product Ah·Bh (for the cv path only)
// CTA 128x128, 128 threads (4 warps, warp tile 64x64), k-chunk 32,
// 3-stage cp.async, occ=2. Grid (2, 2048).
// Stage FULL (32KB): Ahi[0,8K) Alo[8K,16K) Bhi[16K,24K) Blo[24K,32K)
// Stage LITE (16KB): Ahi[0,8K) Bhi[8K,16K)
// ---------------------------------------------------------------------------
#define NKC 8

template <bool FULL>
__global__ __launch_bounds__(128, 2)
void gemm_mma(const __nv_bfloat16* __restrict__ Ah_g, const __nv_bfloat16* __restrict__ Al_g,
              const __nv_bfloat16* __restrict__ Bh_g, const __nv_bfloat16* __restrict__ Bl_g,
              const float* __restrict__ bias,
              __nv_bfloat16* __restrict__ Chi, __nv_bfloat16* __restrict__ Clo)
{
    constexpr u32 STG    = FULL ? 32768u : 16384u;
    constexpr u32 OFF_AL = 8192u;                 // FULL only
    constexpr u32 OFF_BH = FULL ? 16384u : 8192u;
    constexpr u32 OFF_BIAS = 3 * STG;

    extern __shared__ char sm[];
    const uint32_t sb = s2u(sm);
    float* sbias = (float*)(sm + OFF_BIAS);
    const int tid = threadIdx.x, wid = tid >> 5, l = tid & 31;
    const int n0 = blockIdx.x * 128;
    const int m0 = blockIdx.y * 128;

    const int Wm0 = (wid & 1) * 64;
    const int Wn0 = (wid >> 1) * 64;
    const int am = l & 15, aq = l >> 4;
    const int bn = (l & 7) + ((l >> 4) << 3), bq = (l >> 3) & 1;

    sbias[tid] = bias[n0 + tid];

    auto cpAB = [&](int kc, uint32_t stage) {
        const int k0 = kc * 32;
        #pragma unroll
        for (int r = 0; r < 4; r++) {
            int f = tid + r * 128;                 // 0..511
            int row = f >> 2, kq = f & 3;          // row 0..127, 16B chunk 0..3
            u32 so = SWZ64((u32)(row * 64 + kq * 16));
            const size_t asrc = (size_t)(m0 + row) * 256 + k0 + kq * 8;
            const size_t bsrc = (size_t)(n0 + row) * 256 + k0 + kq * 8;
            cpa16(sb + stage + so,          Ah_g + asrc);
            cpa16(sb + stage + OFF_BH + so, Bh_g + bsrc);
            if (FULL) {
                cpa16(sb + stage + OFF_AL + so,          Al_g + asrc);
                cpa16(sb + stage + OFF_BH + 8192u + so,  Bl_g + bsrc);
            }
        }
        asm volatile("cp.async.commit_group;" ::: "memory");
    };

    float acc[4][8][4];
    #pragma unroll
    for (int mt = 0; mt < 4; mt++)
        #pragma unroll
        for (int nt = 0; nt < 8; nt++)
            #pragma unroll
            for (int x = 0; x < 4; x++) acc[mt][nt][x] = 0.f;

    auto compute = [&](uint32_t stage) {
        const uint32_t sA = sb + stage;
        const uint32_t sB = sb + stage + OFF_BH;
        #pragma unroll
        for (int ks = 0; ks < 2; ks++) {
            u32 Ah[4][4], Al[4][4];
            #pragma unroll
            for (int mt = 0; mt < 4; mt++) {
                u32 off = SWZ64((u32)((Wm0 + mt * 16 + am) * 64 + (ks * 2 + aq) * 16));
                ldsm4(Ah[mt], sA + off);
                if (FULL) ldsm4(Al[mt], sA + OFF_AL + off);
            }
            #pragma unroll
            for (int np = 0; np < 4; np++) {
                u32 offb = SWZ64((u32)((Wn0 + np * 16 + bn) * 64 + (ks * 2 + bq) * 16));
                u32 Bh4[4], Bl4[4];
                ldsm4(Bh4, sB + offb);
                if (FULL) ldsm4(Bl4, sB + 8192u + offb);
                #pragma unroll
                for (int mt = 0; mt < 4; mt++) {
                    mma16(acc[mt][2 * np],     Ah[mt], Bh4[0], Bh4[1]);
                    mma16(acc[mt][2 * np + 1], Ah[mt], Bh4[2], Bh4[3]);
                    if (FULL) {
                        mma16(acc[mt][2 * np],     Ah[mt], Bl4[0], Bl4[1]);
                        mma16(acc[mt][2 * np + 1], Ah[mt], Bl4[2], Bl4[3]);
                        mma16(acc[mt][2 * np],     Al[mt], Bh4[0], Bh4[1]);
                        mma16(acc[mt][2 * np + 1], Al[mt], Bh4[2], Bh4[3]);
                    }
                }
            }
        }
    };

    // ---- prologue: fill stages 0,1 ----
    cpAB(0, 0);
    cpAB(1, STG);

    // ---- main loop ----
    for (int kc = 0; kc < NKC; kc++) {
        const uint32_t cur = (u32)(kc % 3) * STG;
        if (kc < NKC - 2) asm volatile("cp.async.wait_group 1;" ::: "memory");
        else              asm volatile("cp.async.wait_group 0;" ::: "memory");
        __syncthreads();
        if (kc + 2 < NKC) cpAB(kc + 2, (u32)((kc + 2) % 3) * STG);
        compute(cur);
    }

    // ---- epilogue: bias + relu + split ----
    #pragma unroll
    for (int mt = 0; mt < 4; mt++) {
        const int r0 = m0 + Wm0 + mt * 16 + (l >> 2);
        #pragma unroll
        for (int nt = 0; nt < 8; nt++) {
            const int col = n0 + Wn0 + nt * 8 + 2 * (l & 3);
            const float b0 = sbias[col - n0], b1 = sbias[col - n0 + 1];
            float x0 = fmaxf(acc[mt][nt][0] + b0, 0.f);
            float x1 = fmaxf(acc[mt][nt][1] + b1, 0.f);
            float x2 = fmaxf(acc[mt][nt][2] + b0, 0.f);
            float x3 = fmaxf(acc[mt][nt][3] + b1, 0.f);
            __nv_bfloat16 h0, h1, h2, h3, l0x, l1x, l2x, l3x;
            split_bf(x0, h0, l0x); split_bf(x1, h1, l1x);
            split_bf(x2, h2, l2x); split_bf(x3, h3, l3x);
            *(u32*)(Chi + (size_t)r0 * 256 + col)       = pack2(h0, h1);
            *(u32*)(Clo + (size_t)r0 * 256 + col)       = pack2(l0x, l1x);
            *(u32*)(Chi + (size_t)(r0 + 8) * 256 + col) = pack2(h2, h3);
            *(u32*)(Clo + (size_t)(r0 + 8) * 256 + col) = pack2(l2x, l3x);
        }
    }
}

// ---------------------------------------------------------------------------
// cv = (relu_c @ wc2) — A given as hi/lo bf16; one warp per row.
// ---------------------------------------------------------------------------
__global__ __launch_bounds__(256)
void colvec_k(const __nv_bfloat16* __restrict__ Ahi, const __nv_bfloat16* __restrict__ Alo,
              const float* __restrict__ w, float* __restrict__ cv)
{
    const int row  = blockIdx.x * 8 + (threadIdx.x >> 5);
    const int lane = threadIdx.x & 31;
    const u32* ah = (const u32*)(Ahi + (size_t)row * ND);
    const u32* al = (const u32*)(Alo + (size_t)row * ND);
    float s = 0.f;
    #pragma unroll
    for (int it = 0; it < 4; it++) {
        int c2 = lane + it * 32;
        float2 a = rec2(ah[c2], al[c2]);
        float2 wv = *(const float2*)(w + c2 * 2);
        s += a.x * wv.x + a.y * wv.y;
    }
    #pragma unroll
    for (int o = 16; o; o >>= 1) s += __shfl_xor_sync(0xffffffffu, s, o);
    if (lane == 0) cv[row] = s;
}

// ---------------------------------------------------------------------------
// Fused attention per batch (unchanged — known correct).
// ---------------------------------------------------------------------------
#define QS 257
#define SMF (2 * NT * QS + NT * ND + NT * 65 + NT + NT * 3)
#define ATTN_SMEM (SMF * 4)

__global__ __launch_bounds__(256, 1)
void attn_k(const __nv_bfloat16* __restrict__ qh, const __nv_bfloat16* __restrict__ ql,
            const __nv_bfloat16* __restrict__ kh, const __nv_bfloat16* __restrict__ kl,
            const __nv_bfloat16* __restrict__ vh, const __nv_bfloat16* __restrict__ vl,
            const float* __restrict__ cv,
            const float* __restrict__ h, const float* __restrict__ coord,
            float* __restrict__ outh, float* __restrict__ outx)
{
    extern __shared__ float smf[];
    float* sq  = smf;                   // 64 x 257
    float* sk  = sq + NT * QS;          // 64 x 257
    float* sv  = sk + NT * QS;          // 64 x 256
    float* ss  = sv + NT * ND;          // 64 x 65
    float* scv = ss + NT * 65;          // 64
    float* sco = scv + NT;              // 64 x 3

    const int b = blockIdx.x, tid = threadIdx.x;
    const size_t base  = (size_t)b * (NT * ND);
    const size_t base2 = base >> 1;

    const u32* qh2 = (const u32*)qh; const u32* ql2 = (const u32*)ql;
    const u32* kh2 = (const u32*)kh; const u32* kl2 = (const u32*)kl;
    const u32* vh2 = (const u32*)vh; const u32* vl2 = (const u32*)vl;

    for (int idx = tid; idx < NT * ND / 2; idx += 256) {
        int r = idx >> 7, c = idx & 127;
        float2 qv = rec2(qh2[base2 + idx], ql2[base2 + idx]);
        float2 kv = rec2(kh2[base2 + idx], kl2[base2 + idx]);
        float2 vv = rec2(vh2[base2 + idx], vl2[base2 + idx]);
        sq[r * QS + 2 * c]     = qv.x;
        sq[r * QS + 2 * c + 1] = qv.y;
        sk[r * QS + 2 * c]     = kv.x;
        sk[r * QS + 2 * c + 1] = kv.y;
        sv[r * 256 + 2 * c]     = vv.x;
        sv[r * 256 + 2 * c + 1] = vv.y;
    }
    if (tid < NT)      scv[tid] = cv[(size_t)b * NT + tid];
    if (tid < NT * 3)  sco[tid] = coord[(size_t)b * (NT * 3) + tid];
    __syncthreads();

    {
        const int i0 = (tid >> 4) * 4, j0 = (tid & 15) * 4;
        float acc[4][4] = {};
        for (int d = 0; d < ND; d++) {
            float qa[4], kb[4];
            #pragma unroll
            for (int ii = 0; ii < 4; ii++) qa[ii] = sq[(i0 + ii) * QS + d];
            #pragma unroll
            for (int jj = 0; jj < 4; jj++) kb[jj] = sk[(j0 + jj) * QS + d];
            #pragma unroll
            for (int ii = 0; ii < 4; ii++)
                #pragma unroll
                for (int jj = 0; jj < 4; jj++) acc[ii][jj] += qa[ii] * kb[jj];
        }
        #pragma unroll
        for (int ii = 0; ii < 4; ii++)
            #pragma unroll
            for (int jj = 0; jj < 4; jj++)
                ss[(i0 + ii) * 65 + j0 + jj] = acc[ii][jj];
    }
    __syncthreads();

    if (tid < NT) {
        const int i = tid;
        float m = -1e30f;
        for (int j = 0; j < NT; j++) m = fmaxf(m, ss[i * 65 + j]);
        float sum = 0.f;
        for (int j = 0; j < NT; j++) {
            float e = expf(ss[i * 65 + j] - m);
            ss[i * 65 + j] = e;
            sum += e;
        }
        float inv = 1.f / sum;
        float wsum = 0.f, w0 = 0.f, w1 = 0.f, w2 = 0.f;
        for (int j = 0; j < NT; j++) {
            float a = ss[i * 65 + j] * inv;
            ss[i * 65 + j] = a;
            float wv = a * scv[j];
            wsum += wv;
            w0 += wv * sco[j * 3 + 0];
            w1 += wv * sco[j * 3 + 1];
            w2 += wv * sco[j * 3 + 2];
        }
        size_t ob = (size_t)b * (NT * 3) + i * 3;
        outx[ob + 0] = sco[i * 3 + 0] + w0 - sco[i * 3 + 0] * wsum;
        outx[ob + 1] = sco[i * 3 + 1] + w1 - sco[i * 3 + 1] * wsum;
        outx[ob + 2] = sco[i * 3 + 2] + w2 - sco[i * 3 + 2] * wsum;
    }
    __syncthreads();

    {
        const int i0 = (tid >> 4) * 4, d0 = (tid & 15) * 16;
        float hacc[4][16] = {};
        for (int j = 0; j < NT; j++) {
            float a[4];
            #pragma unroll
            for (int ii = 0; ii < 4; ii++) a[ii] = ss[(i0 + ii) * 65 + j];
            const float* vr = &sv[j * ND + d0];
            #pragma unroll
            for (int dq = 0; dq < 4; dq++) {
                float4 vv = *(const float4*)(vr + dq * 4);
                #pragma unroll
                for (int ii = 0; ii < 4; ii++) {
                    hacc[ii][dq * 4 + 0] += a[ii] * vv.x;
                    hacc[ii][dq * 4 + 1] += a[ii] * vv.y;
                    hacc[ii][dq * 4 + 2] += a[ii] * vv.z;
                    hacc[ii][dq * 4 + 3] += a[ii] * vv.w;
                }
            }
        }
        #pragma unroll
        for (int ii = 0; ii < 4; ii++) {
            const size_t o = base + (size_t)(i0 + ii) * ND + d0;
            #pragma unroll
            for (int dq = 0; dq < 4; dq++) {
                float4 hv = *(const float4*)(h + o + dq * 4);
                float4 r  = make_float4(hv.x + hacc[ii][dq * 4 + 0],
                                        hv.y + hacc[ii][dq * 4 + 1],
                                        hv.z + hacc[ii][dq * 4 + 2],
                                        hv.w + hacc[ii][dq * 4 + 3]);
                *(float4*)(outh + o + dq * 4) = r;
            }
        }
    }
}

// ---------------------------------------------------------------------------
extern "C" void kernel_launch(void* const* d_in, const int* in_sizes, int n_in,
                              void* d_out, int out_size)
{
    (void)in_sizes; (void)n_in; (void)out_size;
    const float* h     = (const float*)d_in[0];
    const float* coord = (const float*)d_in[1];
    const float* Wq1 = (const float*)d_in[2];
    const float* bq1 = (const float*)d_in[3];
    const float* Wq2 = (const float*)d_in[4];
    const float* bq2 = (const float*)d_in[5];
    const float* Wk1 = (const float*)d_in[6];
    const float* bk1 = (const float*)d_in[7];
    const float* Wk2 = (const float*)d_in[8];
    const float* bk2 = (const float*)d_in[9];
    const float* Wv1 = (const float*)d_in[10];
    const float* bv1 = (const float*)d_in[11];
    const float* Wv2 = (const float*)d_in[12];
    const float* bv2 = (const float*)d_in[13];
    const float* Wc1 = (const float*)d_in[14];
    const float* bc1 = (const float*)d_in[15];
    const float* wc2 = (const float*)d_in[16];

    float* out_h = (float*)d_out;
    float* out_x = out_h + (size_t)BT * ND;

    __nv_bfloat16 *hh, *hl, *th, *tl, *qh, *ql, *kh, *kl, *vh, *vl, *wbh, *wbl;
    float *cv;
    cudaGetSymbolAddress((void**)&hh, g_hh);  cudaGetSymbolAddress((void**)&hl, g_hl);
    cudaGetSymbolAddress((void**)&th, g_th);  cudaGetSymbolAddress((void**)&tl, g_tl);
    cudaGetSymbolAddress((void**)&qh, g_qh);  cudaGetSymbolAddress((void**)&ql, g_ql);
    cudaGetSymbolAddress((void**)&kh, g_kh);  cudaGetSymbolAddress((void**)&kl, g_kl);
    cudaGetSymbolAddress((void**)&vh, g_vh);  cudaGetSymbolAddress((void**)&vl, g_vl);
    cudaGetSymbolAddress((void**)&cv, g_cv);
    cudaGetSymbolAddress((void**)&wbh, g_wbh);
    cudaGetSymbolAddress((void**)&wbl, g_wbl);

    const float* Ws[7] = {Wq1, Wq2, Wk1, Wk2, Wv1, Wv2, Wc1};
    for (int i = 0; i < 7; i++)
        prep_w<<<256, 256>>>(Ws[i], wbh + (size_t)i * ND * ND, wbl + (size_t)i * ND * ND);
    prep_h<<<BT * ND / 1024, 256>>>(h, hh, hl);

    const int SM_FULL = 3 * 32768 + 512;
    const int SM_LITE = 3 * 16384 + 512;
    cudaFuncSetAttribute(gemm_mma<true>,  cudaFuncAttributeMaxDynamicSharedMemorySize, SM_FULL);
    cudaFuncSetAttribute(gemm_mma<false>, cudaFuncAttributeMaxDynamicSharedMemorySize, SM_LITE);
    #define WH(i) (wbh + (size_t)(i) * ND * ND)
    #define WL(i) (wbl + (size_t)(i) * ND * ND)

    dim3 gg(2, 2048);
    gemm_mma<true><<<gg, 128, SM_FULL>>>(hh, hl, WH(0), WL(0), bq1, th, tl);
    gemm_mma<true><<<gg, 128, SM_FULL>>>(th, tl, WH(1), WL(1), bq2, qh, ql);
    gemm_mma<true><<<gg, 128, SM_FULL>>>(hh, hl, WH(2), WL(2), bk1, th, tl);
    gemm_mma<true><<<gg, 128, SM_FULL>>>(th, tl, WH(3), WL(3), bk2, kh, kl);
    gemm_mma<true><<<gg, 128, SM_FULL>>>(hh, hl, WH(4), WL(4), bv1, th, tl);
    gemm_mma<true><<<gg, 128, SM_FULL>>>(th, tl, WH(5), WL(5), bv2, vh, vl);
    gemm_mma<false><<<gg, 128, SM_LITE>>>(vh, vl, WH(6), WL(6), bc1, th, tl);
    colvec_k<<<BT / 8, 256>>>(th, tl, wc2, cv);

    cudaFuncSetAttribute(attn_k, cudaFuncAttributeMaxDynamicSharedMemorySize, ATTN_SMEM);
    attn_k<<<NB, 256, ATTN_SMEM>>>(qh, ql, kh, kl, vh, vl, cv, h, coord, out_h, out_x);
}

// round 9
// speedup vs baseline: 2.6033x; 1.2460x over previous
#include <cuda_runtime.h>
#include <cuda_bf16.h>
#include <math.h>
#include <stdint.h>

typedef unsigned long long u64;
typedef unsigned int u32;
typedef unsigned short u16;

#define NB 4096
#define NT 64
#define ND 256
#define BT (NB * NT)          // 262144 rows

// ---------------- scratch (static device globals; no allocations) ----------
__device__ __nv_bfloat16 g_hh [(size_t)BT * ND];
__device__ __nv_bfloat16 g_hl [(size_t)BT * ND];
__device__ __nv_bfloat16 g_th [(size_t)BT * ND];
__device__ __nv_bfloat16 g_tl [(size_t)BT * ND];
__device__ __nv_bfloat16 g_qh [(size_t)BT * ND];
__device__ __nv_bfloat16 g_ql [(size_t)BT * ND];
__device__ __nv_bfloat16 g_kh [(size_t)BT * ND];
__device__ __nv_bfloat16 g_kl [(size_t)BT * ND];
__device__ __nv_bfloat16 g_vh [(size_t)BT * ND];
__device__ __nv_bfloat16 g_vl [(size_t)BT * ND];
__device__ float g_cv [(size_t)BT];
__device__ __nv_bfloat16 g_wbh[7][ND * ND];   // transposed bf16-hi weights [n][k]
__device__ __nv_bfloat16 g_wbl[7][ND * ND];   // transposed bf16-lo weights [n][k]

// ---------------------------------------------------------------------------
#define SWZ64(o) ((o) ^ (((o) >> 3) & 0x30))

__device__ __forceinline__ uint32_t s2u(const void* p) {
    uint32_t a;
    asm("{ .reg .u64 t; cvta.to.shared.u64 t, %1; cvt.u32.u64 %0, t; }" : "=r"(a) : "l"(p));
    return a;
}
__device__ __forceinline__ void cpa16(uint32_t dst, const void* src) {
    asm volatile("cp.async.cg.shared.global [%0], [%1], 16;" :: "r"(dst), "l"(src));
}
__device__ __forceinline__ void ldsm4(u32 r[4], uint32_t addr) {
    asm volatile("ldmatrix.sync.aligned.m8n8.x4.shared.b16 {%0,%1,%2,%3}, [%4];"
        : "=r"(r[0]), "=r"(r[1]), "=r"(r[2]), "=r"(r[3]) : "r"(addr));
}
__device__ __forceinline__ void mma16(float c[4], const u32 a[4], u32 b0, u32 b1) {
    asm volatile(
        "mma.sync.aligned.m16n8k16.row.col.f32.bf16.bf16.f32 "
        "{%0,%1,%2,%3}, {%4,%5,%6,%7}, {%8,%9}, {%0,%1,%2,%3};"
        : "+f"(c[0]), "+f"(c[1]), "+f"(c[2]), "+f"(c[3])
        : "r"(a[0]), "r"(a[1]), "r"(a[2]), "r"(a[3]), "r"(b0), "r"(b1));
}
__device__ __forceinline__ u32 pack2(__nv_bfloat16 a, __nv_bfloat16 b) {
    return (u32)__bfloat16_as_ushort(a) | ((u32)__bfloat16_as_ushort(b) << 16);
}
__device__ __forceinline__ void split_bf(float x, __nv_bfloat16& hi, __nv_bfloat16& lo) {
    hi = __float2bfloat16_rn(x);
    lo = __float2bfloat16_rn(x - __bfloat162float(hi));
}
__device__ __forceinline__ float2 rec2(u32 h2, u32 l2) {
    __nv_bfloat162 hb = *(__nv_bfloat162*)&h2;
    __nv_bfloat162 lb = *(__nv_bfloat162*)&l2;
    float2 hf = __bfloat1622float2(hb);
    float2 lf = __bfloat1622float2(lb);
    return make_float2(hf.x + lf.x, hf.y + lf.y);
}

// ---------------------------------------------------------------------------
// prep_w / prep_h
// ---------------------------------------------------------------------------
__global__ __launch_bounds__(256)
void prep_w(const float* __restrict__ W, __nv_bfloat16* __restrict__ Bh,
            __nv_bfloat16* __restrict__ Bl)
{
    int idx = blockIdx.x * 256 + threadIdx.x;   // 0..65535
    int k = idx >> 8, n = idx & 255;
    float w = W[idx];
    __nv_bfloat16 hi, lo;
    split_bf(w, hi, lo);
    Bh[n * 256 + k] = hi;
    Bl[n * 256 + k] = lo;
}

__global__ __launch_bounds__(256)
void prep_h(const float* __restrict__ H, __nv_bfloat16* __restrict__ Hh,
            __nv_bfloat16* __restrict__ Hl)
{
    size_t i = ((size_t)blockIdx.x * 256 + threadIdx.x) * 4;
    float4 v = *(const float4*)(H + i);
    __nv_bfloat16 h0, h1, h2, h3, l0, l1, l2, l3;
    split_bf(v.x, h0, l0);
    split_bf(v.y, h1, l1);
    split_bf(v.z, h2, l2);
    split_bf(v.w, h3, l3);
    *(uint2*)(Hh + i) = make_uint2(pack2(h0, h1), pack2(h2, h3));
    *(uint2*)(Hl + i) = make_uint2(pack2(l0, l1), pack2(l2, l3));
}

// ---------------------------------------------------------------------------
// gemm_mma<FULL>  (unchanged from R8 — passing, at legacy-mma roofline)
// ---------------------------------------------------------------------------
#define NKC 8

template <bool FULL>
__global__ __launch_bounds__(128, 2)
void gemm_mma(const __nv_bfloat16* __restrict__ Ah_g, const __nv_bfloat16* __restrict__ Al_g,
              const __nv_bfloat16* __restrict__ Bh_g, const __nv_bfloat16* __restrict__ Bl_g,
              const float* __restrict__ bias,
              __nv_bfloat16* __restrict__ Chi, __nv_bfloat16* __restrict__ Clo)
{
    constexpr u32 STG    = FULL ? 32768u : 16384u;
    constexpr u32 OFF_AL = 8192u;
    constexpr u32 OFF_BH = FULL ? 16384u : 8192u;
    constexpr u32 OFF_BIAS = 3 * STG;

    extern __shared__ char sm[];
    const uint32_t sb = s2u(sm);
    float* sbias = (float*)(sm + OFF_BIAS);
    const int tid = threadIdx.x, wid = tid >> 5, l = tid & 31;
    const int n0 = blockIdx.x * 128;
    const int m0 = blockIdx.y * 128;

    const int Wm0 = (wid & 1) * 64;
    const int Wn0 = (wid >> 1) * 64;
    const int am = l & 15, aq = l >> 4;
    const int bn = (l & 7) + ((l >> 4) << 3), bq = (l >> 3) & 1;

    sbias[tid] = bias[n0 + tid];

    auto cpAB = [&](int kc, uint32_t stage) {
        const int k0 = kc * 32;
        #pragma unroll
        for (int r = 0; r < 4; r++) {
            int f = tid + r * 128;
            int row = f >> 2, kq = f & 3;
            u32 so = SWZ64((u32)(row * 64 + kq * 16));
            const size_t asrc = (size_t)(m0 + row) * 256 + k0 + kq * 8;
            const size_t bsrc = (size_t)(n0 + row) * 256 + k0 + kq * 8;
            cpa16(sb + stage + so,          Ah_g + asrc);
            cpa16(sb + stage + OFF_BH + so, Bh_g + bsrc);
            if (FULL) {
                cpa16(sb + stage + OFF_AL + so,          Al_g + asrc);
                cpa16(sb + stage + OFF_BH + 8192u + so,  Bl_g + bsrc);
            }
        }
        asm volatile("cp.async.commit_group;" ::: "memory");
    };

    float acc[4][8][4];
    #pragma unroll
    for (int mt = 0; mt < 4; mt++)
        #pragma unroll
        for (int nt = 0; nt < 8; nt++)
            #pragma unroll
            for (int x = 0; x < 4; x++) acc[mt][nt][x] = 0.f;

    auto compute = [&](uint32_t stage) {
        const uint32_t sA = sb + stage;
        const uint32_t sB = sb + stage + OFF_BH;
        #pragma unroll
        for (int ks = 0; ks < 2; ks++) {
            u32 Ah[4][4], Al[4][4];
            #pragma unroll
            for (int mt = 0; mt < 4; mt++) {
                u32 off = SWZ64((u32)((Wm0 + mt * 16 + am) * 64 + (ks * 2 + aq) * 16));
                ldsm4(Ah[mt], sA + off);
                if (FULL) ldsm4(Al[mt], sA + OFF_AL + off);
            }
            #pragma unroll
            for (int np = 0; np < 4; np++) {
                u32 offb = SWZ64((u32)((Wn0 + np * 16 + bn) * 64 + (ks * 2 + bq) * 16));
                u32 Bh4[4], Bl4[4];
                ldsm4(Bh4, sB + offb);
                if (FULL) ldsm4(Bl4, sB + 8192u + offb);
                #pragma unroll
                for (int mt = 0; mt < 4; mt++) {
                    mma16(acc[mt][2 * np],     Ah[mt], Bh4[0], Bh4[1]);
                    mma16(acc[mt][2 * np + 1], Ah[mt], Bh4[2], Bh4[3]);
                    if (FULL) {
                        mma16(acc[mt][2 * np],     Ah[mt], Bl4[0], Bl4[1]);
                        mma16(acc[mt][2 * np + 1], Ah[mt], Bl4[2], Bl4[3]);
                        mma16(acc[mt][2 * np],     Al[mt], Bh4[0], Bh4[1]);
                        mma16(acc[mt][2 * np + 1], Al[mt], Bh4[2], Bh4[3]);
                    }
                }
            }
        }
    };

    cpAB(0, 0);
    cpAB(1, STG);

    for (int kc = 0; kc < NKC; kc++) {
        const uint32_t cur = (u32)(kc % 3) * STG;
        if (kc < NKC - 2) asm volatile("cp.async.wait_group 1;" ::: "memory");
        else              asm volatile("cp.async.wait_group 0;" ::: "memory");
        __syncthreads();
        if (kc + 2 < NKC) cpAB(kc + 2, (u32)((kc + 2) % 3) * STG);
        compute(cur);
    }

    #pragma unroll
    for (int mt = 0; mt < 4; mt++) {
        const int r0 = m0 + Wm0 + mt * 16 + (l >> 2);
        #pragma unroll
        for (int nt = 0; nt < 8; nt++) {
            const int col = n0 + Wn0 + nt * 8 + 2 * (l & 3);
            const float b0 = sbias[col - n0], b1 = sbias[col - n0 + 1];
            float x0 = fmaxf(acc[mt][nt][0] + b0, 0.f);
            float x1 = fmaxf(acc[mt][nt][1] + b1, 0.f);
            float x2 = fmaxf(acc[mt][nt][2] + b0, 0.f);
            float x3 = fmaxf(acc[mt][nt][3] + b1, 0.f);
            __nv_bfloat16 h0, h1, h2, h3, l0x, l1x, l2x, l3x;
            split_bf(x0, h0, l0x); split_bf(x1, h1, l1x);
            split_bf(x2, h2, l2x); split_bf(x3, h3, l3x);
            *(u32*)(Chi + (size_t)r0 * 256 + col)       = pack2(h0, h1);
            *(u32*)(Clo + (size_t)r0 * 256 + col)       = pack2(l0x, l1x);
            *(u32*)(Chi + (size_t)(r0 + 8) * 256 + col) = pack2(h2, h3);
            *(u32*)(Clo + (size_t)(r0 + 8) * 256 + col) = pack2(l2x, l3x);
        }
    }
}

// ---------------------------------------------------------------------------
// cv = (relu_c @ wc2) — A given as hi/lo bf16; one warp per row.
// ---------------------------------------------------------------------------
__global__ __launch_bounds__(256)
void colvec_k(const __nv_bfloat16* __restrict__ Ahi, const __nv_bfloat16* __restrict__ Alo,
              const float* __restrict__ w, float* __restrict__ cv)
{
    const int row  = blockIdx.x * 8 + (threadIdx.x >> 5);
    const int lane = threadIdx.x & 31;
    const u32* ah = (const u32*)(Ahi + (size_t)row * ND);
    const u32* al = (const u32*)(Alo + (size_t)row * ND);
    float s = 0.f;
    #pragma unroll
    for (int it = 0; it < 4; it++) {
        int c2 = lane + it * 32;
        float2 a = rec2(ah[c2], al[c2]);
        float2 wv = *(const float2*)(w + c2 * 2);
        s += a.x * wv.x + a.y * wv.y;
    }
    #pragma unroll
    for (int o = 16; o; o >>= 1) s += __shfl_xor_sync(0xffffffffu, s, o);
    if (lane == 0) cv[row] = s;
}

// ---------------------------------------------------------------------------
// attn_k: tensor-core attention. 256 threads (8 warps), occ 1.
// SMEM (bytes): QH 0 | QL 32768 | KH 65536 | KL 98304 | VTH 131072 |
//               VTL 163840 | SS 196608 (fp32 64x65) | SCV 213248 | SCO 213504
// After softmax, alpha bf16 hi/lo overwrite QH/QL (q is dead).
// Chunk layout identical to gemm: [kc][row][64B] with SW64 swizzle.
// ---------------------------------------------------------------------------
#define A_QH  0u
#define A_QL  32768u
#define A_KH  65536u
#define A_KL  98304u
#define A_VTH 131072u
#define A_VTL 163840u
#define A_SS  196608u
#define A_SCV 213248u
#define A_SCO 213504u
#define ATTN_SMEM 214272

__global__ __launch_bounds__(256, 1)
void attn_k(const __nv_bfloat16* __restrict__ qh_g, const __nv_bfloat16* __restrict__ ql_g,
            const __nv_bfloat16* __restrict__ kh_g, const __nv_bfloat16* __restrict__ kl_g,
            const __nv_bfloat16* __restrict__ vh_g, const __nv_bfloat16* __restrict__ vl_g,
            const float* __restrict__ cv,
            const float* __restrict__ h, const float* __restrict__ coord,
            float* __restrict__ outh, float* __restrict__ outx)
{
    extern __shared__ char smc[];
    const u32 sb = s2u(smc);
    float* ss  = (float*)(smc + A_SS);
    float* scv = (float*)(smc + A_SCV);
    float* sco = (float*)(smc + A_SCO);

    const int b = blockIdx.x, tid = threadIdx.x, wid = tid >> 5, l = tid & 31;
    const size_t base  = (size_t)b * (NT * ND);
    const size_t base2 = base >> 1;

    // ---- load q/k hi/lo into chunked SW64 tiles via cp.async ----
    {
        const __nv_bfloat16* srcs[4] = {qh_g + base, ql_g + base, kh_g + base, kl_g + base};
        const u32 dsts[4] = {A_QH, A_QL, A_KH, A_KL};
        #pragma unroll
        for (int t = 0; t < 4; t++) {
            #pragma unroll
            for (int r = 0; r < 8; r++) {
                int g = tid + r * 256;          // 0..2047 : 64 rows x 32 granules
                int row = g >> 5, t16 = g & 31;
                int kc = t16 >> 2, q16 = t16 & 3;
                cpa16(sb + dsts[t] + (u32)kc * 4096u + SWZ64((u32)(row * 64 + q16 * 16)),
                      srcs[t] + row * 256 + t16 * 8);
            }
        }
        asm volatile("cp.async.commit_group;" ::: "memory");
    }

    // ---- v transposed into VT tiles (rows = d, k = j) ----
    {
        const u32* vh2 = (const u32*)vh_g;
        const u32* vl2 = (const u32*)vl_g;
        for (int idx = tid; idx < 8192; idx += 256) {
            int j = idx >> 7, c = idx & 127;
            u32 xh = vh2[base2 + idx], xl = vl2[base2 + idx];
            int kc = j >> 5, jj = j & 31, d = 2 * c;
            u32 o0 = (u32)kc * 16384u + SWZ64((u32)(d * 64 + jj * 2));
            u32 o1 = (u32)kc * 16384u + SWZ64((u32)((d + 1) * 64 + jj * 2));
            *(u16*)(smc + A_VTH + o0) = (u16)(xh & 0xffffu);
            *(u16*)(smc + A_VTH + o1) = (u16)(xh >> 16);
            *(u16*)(smc + A_VTL + o0) = (u16)(xl & 0xffffu);
            *(u16*)(smc + A_VTL + o1) = (u16)(xl >> 16);
        }
    }
    if (tid < NT)     scv[tid] = cv[(size_t)b * NT + tid];
    if (tid < NT * 3) sco[tid] = coord[(size_t)b * (NT * 3) + tid];
    asm volatile("cp.async.wait_group 0;" ::: "memory");
    __syncthreads();

    const int am = l & 15, aq = l >> 4;
    const int bn = (l & 7) + ((l >> 4) << 3), bq = (l >> 3) & 1;

    // ---- QK^T : 64x64x256, bf16x3, warp tile m16 x n32 ----
    {
        const int Wm0 = (wid & 3) * 16, Wn0 = (wid >> 2) * 32;
        float acc[4][4] = {};
        for (int kc = 0; kc < 8; kc++) {
            #pragma unroll
            for (int ks = 0; ks < 2; ks++) {
                u32 aoff = (u32)kc * 4096u + SWZ64((u32)((Wm0 + am) * 64 + (ks * 2 + aq) * 16));
                u32 aH[4], aL[4];
                ldsm4(aH, sb + A_QH + aoff);
                ldsm4(aL, sb + A_QL + aoff);
                #pragma unroll
                for (int np = 0; np < 2; np++) {
                    u32 boff = (u32)kc * 4096u + SWZ64((u32)((Wn0 + np * 16 + bn) * 64 + (ks * 2 + bq) * 16));
                    u32 bH[4], bL[4];
                    ldsm4(bH, sb + A_KH + boff);
                    ldsm4(bL, sb + A_KL + boff);
                    mma16(acc[2 * np],     aH, bH[0], bH[1]);
                    mma16(acc[2 * np + 1], aH, bH[2], bH[3]);
                    mma16(acc[2 * np],     aH, bL[0], bL[1]);
                    mma16(acc[2 * np + 1], aH, bL[2], bL[3]);
                    mma16(acc[2 * np],     aL, bH[0], bH[1]);
                    mma16(acc[2 * np + 1], aL, bH[2], bH[3]);
                }
            }
        }
        const int r0 = Wm0 + (l >> 2);
        #pragma unroll
        for (int nt = 0; nt < 4; nt++) {
            const int col = Wn0 + nt * 8 + 2 * (l & 3);
            ss[r0 * 65 + col]           = acc[nt][0];
            ss[r0 * 65 + col + 1]       = acc[nt][1];
            ss[(r0 + 8) * 65 + col]     = acc[nt][2];
            ss[(r0 + 8) * 65 + col + 1] = acc[nt][3];
        }
    }
    __syncthreads();

    // ---- softmax + coord + alpha split into AH/AL (= QH/QL region) ----
    if (tid < NT) {
        const int i = tid;
        float m = -1e30f;
        for (int j = 0; j < NT; j++) m = fmaxf(m, ss[i * 65 + j]);
        float sum = 0.f;
        for (int j = 0; j < NT; j++) {
            float e = expf(ss[i * 65 + j] - m);
            ss[i * 65 + j] = e;
            sum += e;
        }
        const float inv = 1.f / sum;
        float wsum = 0.f, w0 = 0.f, w1 = 0.f, w2 = 0.f;
        for (int j = 0; j < NT; j += 2) {
            float a0 = ss[i * 65 + j] * inv;
            float a1 = ss[i * 65 + j + 1] * inv;
            float wv0 = a0 * scv[j], wv1 = a1 * scv[j + 1];
            wsum += wv0 + wv1;
            w0 += wv0 * sco[j * 3 + 0] + wv1 * sco[(j + 1) * 3 + 0];
            w1 += wv0 * sco[j * 3 + 1] + wv1 * sco[(j + 1) * 3 + 1];
            w2 += wv0 * sco[j * 3 + 2] + wv1 * sco[(j + 1) * 3 + 2];
            __nv_bfloat16 h0, l0, h1, l1;
            split_bf(a0, h0, l0);
            split_bf(a1, h1, l1);
            int kc = j >> 5, jj = j & 31;
            u32 off = (u32)kc * 4096u + SWZ64((u32)(i * 64 + jj * 2));
            *(u32*)(smc + A_QH + off) = pack2(h0, h1);
            *(u32*)(smc + A_QL + off) = pack2(l0, l1);
        }
        size_t ob = (size_t)b * (NT * 3) + i * 3;
        outx[ob + 0] = sco[i * 3 + 0] + w0 - sco[i * 3 + 0] * wsum;
        outx[ob + 1] = sco[i * 3 + 1] + w1 - sco[i * 3 + 1] * wsum;
        outx[ob + 2] = sco[i * 3 + 2] + w2 - sco[i * 3 + 2] * wsum;
    }
    __syncthreads();

    // ---- alpha @ v : 64x256x64, bf16x3, warp tile m16 x n128 ----
    {
        const int Wm0 = (wid & 3) * 16, Wn0 = (wid >> 2) * 128;
        float acc[16][4];
        #pragma unroll
        for (int nb = 0; nb < 16; nb++)
            #pragma unroll
            for (int x = 0; x < 4; x++) acc[nb][x] = 0.f;

        #pragma unroll
        for (int kc = 0; kc < 2; kc++) {
            #pragma unroll
            for (int ks = 0; ks < 2; ks++) {
                u32 aoff = (u32)kc * 4096u + SWZ64((u32)((Wm0 + am) * 64 + (ks * 2 + aq) * 16));
                u32 aH[4], aL[4];
                ldsm4(aH, sb + A_QH + aoff);
                ldsm4(aL, sb + A_QL + aoff);
                #pragma unroll
                for (int np = 0; np < 8; np++) {
                    u32 boff = (u32)kc * 16384u + SWZ64((u32)((Wn0 + np * 16 + bn) * 64 + (ks * 2 + bq) * 16));
                    u32 bH[4], bL[4];
                    ldsm4(bH, sb + A_VTH + boff);
                    ldsm4(bL, sb + A_VTL + boff);
                    mma16(acc[2 * np],     aH, bH[0], bH[1]);
                    mma16(acc[2 * np + 1], aH, bH[2], bH[3]);
                    mma16(acc[2 * np],     aH, bL[0], bL[1]);
                    mma16(acc[2 * np + 1], aH, bL[2], bL[3]);
                    mma16(acc[2 * np],     aL, bH[0], bH[1]);
                    mma16(acc[2 * np + 1], aL, bH[2], bH[3]);
                }
            }
        }
        const int r0 = Wm0 + (l >> 2);
        #pragma unroll
        for (int nb = 0; nb < 16; nb++) {
            const int col = Wn0 + nb * 8 + 2 * (l & 3);
            const size_t o0 = base + (size_t)r0 * 256 + col;
            const size_t o1 = base + (size_t)(r0 + 8) * 256 + col;
            float2 h0 = *(const float2*)(h + o0);
            float2 h1 = *(const float2*)(h + o1);
            *(float2*)(outh + o0) = make_float2(h0.x + acc[nb][0], h0.y + acc[nb][1]);
            *(float2*)(outh + o1) = make_float2(h1.x + acc[nb][2], h1.y + acc[nb][3]);
        }
    }
}

// ---------------------------------------------------------------------------
extern "C" void kernel_launch(void* const* d_in, const int* in_sizes, int n_in,
                              void* d_out, int out_size)
{
    (void)in_sizes; (void)n_in; (void)out_size;
    const float* h     = (const float*)d_in[0];
    const float* coord = (const float*)d_in[1];
    const float* Wq1 = (const float*)d_in[2];
    const float* bq1 = (const float*)d_in[3];
    const float* Wq2 = (const float*)d_in[4];
    const float* bq2 = (const float*)d_in[5];
    const float* Wk1 = (const float*)d_in[6];
    const float* bk1 = (const float*)d_in[7];
    const float* Wk2 = (const float*)d_in[8];
    const float* bk2 = (const float*)d_in[9];
    const float* Wv1 = (const float*)d_in[10];
    const float* bv1 = (const float*)d_in[11];
    const float* Wv2 = (const float*)d_in[12];
    const float* bv2 = (const float*)d_in[13];
    const float* Wc1 = (const float*)d_in[14];
    const float* bc1 = (const float*)d_in[15];
    const float* wc2 = (const float*)d_in[16];

    float* out_h = (float*)d_out;
    float* out_x = out_h + (size_t)BT * ND;

    __nv_bfloat16 *hh, *hl, *th, *tl, *qh, *ql, *kh, *kl, *vh, *vl, *wbh, *wbl;
    float *cv;
    cudaGetSymbolAddress((void**)&hh, g_hh);  cudaGetSymbolAddress((void**)&hl, g_hl);
    cudaGetSymbolAddress((void**)&th, g_th);  cudaGetSymbolAddress((void**)&tl, g_tl);
    cudaGetSymbolAddress((void**)&qh, g_qh);  cudaGetSymbolAddress((void**)&ql, g_ql);
    cudaGetSymbolAddress((void**)&kh, g_kh);  cudaGetSymbolAddress((void**)&kl, g_kl);
    cudaGetSymbolAddress((void**)&vh, g_vh);  cudaGetSymbolAddress((void**)&vl, g_vl);
    cudaGetSymbolAddress((void**)&cv, g_cv);
    cudaGetSymbolAddress((void**)&wbh, g_wbh);
    cudaGetSymbolAddress((void**)&wbl, g_wbl);

    const float* Ws[7] = {Wq1, Wq2, Wk1, Wk2, Wv1, Wv2, Wc1};
    for (int i = 0; i < 7; i++)
        prep_w<<<256, 256>>>(Ws[i], wbh + (size_t)i * ND * ND, wbl + (size_t)i * ND * ND);
    prep_h<<<BT * ND / 1024, 256>>>(h, hh, hl);

    const int SM_FULL = 3 * 32768 + 512;
    const int SM_LITE = 3 * 16384 + 512;
    cudaFuncSetAttribute(gemm_mma<true>,  cudaFuncAttributeMaxDynamicSharedMemorySize, SM_FULL);
    cudaFuncSetAttribute(gemm_mma<false>, cudaFuncAttributeMaxDynamicSharedMemorySize, SM_LITE);
    #define WH(i) (wbh + (size_t)(i) * ND * ND)
    #define WL(i) (wbl + (size_t)(i) * ND * ND)

    dim3 gg(2, 2048);
    gemm_mma<true><<<gg, 128, SM_FULL>>>(hh, hl, WH(0), WL(0), bq1, th, tl);
    gemm_mma<true><<<gg, 128, SM_FULL>>>(th, tl, WH(1), WL(1), bq2, qh, ql);
    gemm_mma<true><<<gg, 128, SM_FULL>>>(hh, hl, WH(2), WL(2), bk1, th, tl);
    gemm_mma<true><<<gg, 128, SM_FULL>>>(th, tl, WH(3), WL(3), bk2, kh, kl);
    gemm_mma<true><<<gg, 128, SM_FULL>>>(hh, hl, WH(4), WL(4), bv1, th, tl);
    gemm_mma<true><<<gg, 128, SM_FULL>>>(th, tl, WH(5), WL(5), bv2, vh, vl);
    gemm_mma<false><<<gg, 128, SM_LITE>>>(vh, vl, WH(6), WL(6), bc1, th, tl);
    colvec_k<<<BT / 8, 256>>>(th, tl, wc2, cv);

    cudaFuncSetAttribute(attn_k, cudaFuncAttributeMaxDynamicSharedMemorySize, ATTN_SMEM);
    attn_k<<<NB, 256, ATTN_SMEM>>>(qh, ql, kh, kl, vh, vl, cv, h, coord, out_h, out_x);
}